// round 10
// baseline (speedup 1.0000x reference)
#include <cuda_runtime.h>
#include <cuda_bf16.h>
#include <stdint.h>
#include <math.h>

#define BATCH   2
#define S_LEN   2048
#define DMODEL  1024
#define NHEAD   16
#define HDIM    64
#define MROWS   (BATCH * S_LEN)   // 4096
#define KBIG    (3 * DMODEL)      // 3072: A=[hi|lo|hi], B=[hi|hi|lo]
#define KCH     (KBIG / 64)       // 48 chunks of K=64
#define NBH     (BATCH * NHEAD)   // 32

// ---------------- scratch (allocation-free device globals) ----------------
__device__ __align__(16) __nv_bfloat16 g_xbig[MROWS * KBIG];   // 24MB
__device__ __align__(16) __nv_bfloat16 g_cbig[MROWS * KBIG];   // 24MB
__device__ __align__(16) __nv_bfloat16 g_wqb[DMODEL * KBIG];
__device__ __align__(16) __nv_bfloat16 g_wkb[DMODEL * KBIG];
__device__ __align__(16) __nv_bfloat16 g_wvb[DMODEL * KBIG];
__device__ __align__(16) __nv_bfloat16 g_wob[DMODEL * KBIG];
__device__ float g_v[MROWS * DMODEL];
// attention bf16 hi/lo operands
__device__ __align__(16) __nv_bfloat16 g_qh[NBH * S_LEN * HDIM];
__device__ __align__(16) __nv_bfloat16 g_ql[NBH * S_LEN * HDIM];
__device__ __align__(16) __nv_bfloat16 g_kh[NBH * S_LEN * HDIM];
__device__ __align__(16) __nv_bfloat16 g_kl[NBH * S_LEN * HDIM];
__device__ __align__(16) __nv_bfloat16 g_vth[NBH * HDIM * S_LEN];  // transposed
__device__ __align__(16) __nv_bfloat16 g_vtl[NBH * HDIM * S_LEN];

// ---------------- PTX helpers (all legal on plain sm_103) ----------------
__device__ __forceinline__ uint32_t smem_u32(const void* p) {
    uint32_t a;
    asm("{ .reg .u64 t; cvta.to.shared.u64 t, %1; cvt.u32.u64 %0, t; }" : "=r"(a) : "l"(p));
    return a;
}
__device__ __forceinline__ void cp_async16(uint32_t saddr, const void* gaddr) {
    asm volatile("cp.async.cg.shared.global [%0], [%1], 16;" :: "r"(saddr), "l"(gaddr));
}
__device__ __forceinline__ void cp_commit() {
    asm volatile("cp.async.commit_group;" ::: "memory");
}
__device__ __forceinline__ void cp_wait0() {
    asm volatile("cp.async.wait_group 0;" ::: "memory");
}
__device__ __forceinline__ void cp_wait1() {
    asm volatile("cp.async.wait_group 1;" ::: "memory");
}
__device__ __forceinline__ void ldm_x4(uint32_t& r0, uint32_t& r1, uint32_t& r2, uint32_t& r3,
                                       uint32_t addr) {
    asm volatile("ldmatrix.sync.aligned.m8n8.x4.shared.b16 {%0,%1,%2,%3}, [%4];"
                 : "=r"(r0), "=r"(r1), "=r"(r2), "=r"(r3) : "r"(addr));
}
__device__ __forceinline__ void mma_bf16(float* d, const uint32_t* a, const uint32_t* b) {
    asm volatile(
        "mma.sync.aligned.m16n8k16.row.col.f32.bf16.bf16.f32 "
        "{%0,%1,%2,%3}, {%4,%5,%6,%7}, {%8,%9}, {%0,%1,%2,%3};"
        : "+f"(d[0]), "+f"(d[1]), "+f"(d[2]), "+f"(d[3])
        : "r"(a[0]), "r"(a[1]), "r"(a[2]), "r"(a[3]), "r"(b[0]), "r"(b[1]));
}
__device__ __forceinline__ uint32_t packbf2(float a, float b) {
    __nv_bfloat162 t = __floats2bfloat162_rn(a, b);
    return *reinterpret_cast<uint32_t*>(&t);
}
__device__ __forceinline__ float bf16rt(float v) {
    return __bfloat162float(__float2bfloat16(v));
}

// ---------------- conversion: fp32 -> bf16 hi/lo packed, K'=3072 ----------------
__global__ __launch_bounds__(256) void cvt_x(const float* __restrict__ X,
                                             __nv_bfloat16* __restrict__ O)
{
    int idx = blockIdx.x * 256 + threadIdx.x;
    int m   = idx >> 8;
    int k4  = (idx & 255) << 2;
    float4 v = *(const float4*)(X + (size_t)m * DMODEL + k4);
    float f[4] = {v.x, v.y, v.z, v.w};
    __nv_bfloat16 h[4], l[4];
#pragma unroll
    for (int i = 0; i < 4; i++) {
        h[i] = __float2bfloat16(f[i]);
        l[i] = __float2bfloat16(f[i] - __bfloat162float(h[i]));
    }
    __nv_bfloat162 h01, h23, l01, l23;
    h01.x = h[0]; h01.y = h[1]; h23.x = h[2]; h23.y = h[3];
    l01.x = l[0]; l01.y = l[1]; l23.x = l[2]; l23.y = l[3];
    __nv_bfloat162* p0 = (__nv_bfloat162*)(O + (size_t)m * KBIG + k4);
    __nv_bfloat162* p1 = (__nv_bfloat162*)(O + (size_t)m * KBIG + DMODEL + k4);
    __nv_bfloat162* p2 = (__nv_bfloat162*)(O + (size_t)m * KBIG + 2 * DMODEL + k4);
    p0[0] = h01; p0[1] = h23;      // hi
    p1[0] = l01; p1[1] = l23;      // lo
    p2[0] = h01; p2[1] = h23;      // hi
}

__global__ __launch_bounds__(256) void cvt_w(const float* __restrict__ W,
                                             __nv_bfloat16* __restrict__ O)
{
    __shared__ float t[32][33];
    int n0 = blockIdx.x * 32, k0 = blockIdx.y * 32;
    int tx = threadIdx.x, ty = threadIdx.y;
#pragma unroll
    for (int i = 0; i < 4; i++)
        t[ty + 8 * i][tx] = W[(size_t)(k0 + ty + 8 * i) * DMODEL + n0 + tx];
    __syncthreads();
#pragma unroll
    for (int i = 0; i < 4; i++) {
        int n = n0 + ty + 8 * i, k = k0 + tx;
        float v = t[tx][ty + 8 * i];
        __nv_bfloat16 h = __float2bfloat16(v);
        __nv_bfloat16 l = __float2bfloat16(v - __bfloat162float(h));
        O[(size_t)n * KBIG + k]              = h;
        O[(size_t)n * KBIG + DMODEL + k]     = h;
        O[(size_t)n * KBIG + 2 * DMODEL + k] = l;
    }
}

// V fp32 [b*S+s][h*64+d] -> transposed bf16 hi/lo [bh][d][s]
__global__ __launch_bounds__(256) void cvt_vt(const float* __restrict__ V,
                                              __nv_bfloat16* __restrict__ Oh,
                                              __nv_bfloat16* __restrict__ Ol)
{
    __shared__ float t[64][65];
    const int tid = threadIdx.x;
    const int s0  = blockIdx.x * 64;
    const int bh  = blockIdx.y;
    const int b   = bh >> 4, h = bh & 15;
#pragma unroll
    for (int i = 0; i < 16; i++) {
        int u = tid + i * 256;
        int s = u >> 6, d = u & 63;
        t[s][d] = V[((size_t)(b * S_LEN) + s0 + s) * DMODEL + h * 64 + d];
    }
    __syncthreads();
    const int d  = tid >> 2;
    const int jg = tid & 3;
    __nv_bfloat16 hv[16], lv[16];
#pragma unroll
    for (int jj = 0; jj < 16; jj++) {
        float v = t[jg * 16 + jj][d];
        hv[jj] = __float2bfloat16(v);
        lv[jj] = __float2bfloat16(v - __bfloat162float(hv[jj]));
    }
    size_t dst = ((size_t)bh * HDIM + d) * S_LEN + s0 + jg * 16;
    ((uint4*)(Oh + dst))[0] = ((uint4*)hv)[0];
    ((uint4*)(Oh + dst))[1] = ((uint4*)hv)[1];
    ((uint4*)(Ol + dst))[0] = ((uint4*)lv)[0];
    ((uint4*)(Ol + dst))[1] = ((uint4*)lv)[1];
}

// ---------------- bf16 HMMA GEMM, 3-stage cp.async pipeline ----------------
// CTA 128x128, K chunk 64, 8 warps (64x32 warp tile).
// fp32_only=0: z=0 -> (H0,L0) head-split bf16; z=1 -> (H1,L1); z=2 -> Cf fp32.
// fp32_only=1: Cf fp32 (+bias).
__global__ __launch_bounds__(256) void gemm_mma(
    const __nv_bfloat16* __restrict__ A,
    const __nv_bfloat16* __restrict__ B0, const __nv_bfloat16* __restrict__ B1,
    const __nv_bfloat16* __restrict__ B2,
    float* Cf,
    __nv_bfloat16* H0, __nv_bfloat16* L0,
    __nv_bfloat16* H1, __nv_bfloat16* L1,
    const float* __restrict__ bias, int fp32_only)
{
    extern __shared__ __align__(1024) unsigned char dsm[];

    const __nv_bfloat16* Bt = (blockIdx.z == 0) ? B0 : (blockIdx.z == 1) ? B1 : B2;

    const int tid  = threadIdx.x;
    const int wid  = tid >> 5;
    const int lane = tid & 31;
    const int bm   = blockIdx.y, bn = blockIdx.x;
    const int wm   = (wid & 1) * 64;
    const int wn   = (wid >> 1) * 32;

    const uint32_t s0  = smem_u32(dsm);
    const uint32_t sS0 = (s0 + 1023) & ~1023u;    // stage base; A at +0, B at +16384

    // ---- producer addressing ----
    const int row0 = tid >> 3;
    const int seg  = tid & 7;
    const uint32_t swz = (uint32_t)((seg ^ (row0 & 7)) << 4);
    const __nv_bfloat16* aG = A  + (size_t)(bm * 128 + row0) * KBIG + seg * 8;
    const __nv_bfloat16* bG = Bt + (size_t)(bn * 128 + row0) * KBIG + seg * 8;
    const uint32_t stA = sS0 + row0 * 128 + swz;
    const uint32_t stB = sS0 + 16384 + row0 * 128 + swz;

    // ---- consumer addressing ----
    uint32_t aBase[4], aMask[4];
#pragma unroll
    for (int mi = 0; mi < 4; mi++) {
        int r = wm + mi * 16 + (lane & 15);
        aBase[mi] = sS0 + r * 128;
        aMask[mi] = r & 7;
    }
    // B: ldm_x4 pairs; pair p covers cols wn+p*16 .. +15
    uint32_t bBase[2], bMask[2];
#pragma unroll
    for (int p = 0; p < 2; p++) {
        int r = wn + p * 16 + ((lane >> 4) << 3) + (lane & 7);
        bBase[p] = sS0 + 16384 + r * 128;
        bMask[p] = r & 7;
    }
    const uint32_t kselA = (lane >> 4);
    const uint32_t kaddB = (lane >> 3) & 1;

    float acc[4][4][4];
#pragma unroll
    for (int mi = 0; mi < 4; mi++)
#pragma unroll
        for (int ni = 0; ni < 4; ni++)
#pragma unroll
            for (int r = 0; r < 4; r++) acc[mi][ni][r] = 0.0f;

    auto load_chunk = [&](int c, int buf) {
        const uint32_t bo = (uint32_t)buf * 32768;
        const __nv_bfloat16* ap = aG + c * 64;
        const __nv_bfloat16* bp = bG + c * 64;
#pragma unroll
        for (int i = 0; i < 4; i++) {
            cp_async16(stA + bo + i * 4096, ap + (size_t)i * 32 * KBIG);
            cp_async16(stB + bo + i * 4096, bp + (size_t)i * 32 * KBIG);
        }
        cp_commit();
    };

    load_chunk(0, 0);
    load_chunk(1, 1);
    int buf = 0;
    for (int c = 0; c < KCH; c++) {
        if (c + 1 < KCH) cp_wait1(); else cp_wait0();
        __syncthreads();
        if (c + 2 < KCH) load_chunk(c + 2, (c + 2) % 3);
        const uint32_t bo = (uint32_t)buf * 32768;
#pragma unroll
        for (int ks = 0; ks < 4; ks++) {
            uint32_t a[4][4], b[4][2];
#pragma unroll
            for (int mi = 0; mi < 4; mi++) {
                uint32_t u = (uint32_t)(ks * 2) + kselA;
                ldm_x4(a[mi][0], a[mi][1], a[mi][2], a[mi][3],
                       aBase[mi] + bo + ((u ^ aMask[mi]) << 4));
            }
#pragma unroll
            for (int p = 0; p < 2; p++) {
                uint32_t u = (uint32_t)(ks * 2) + kaddB;
                ldm_x4(b[2 * p][0], b[2 * p][1], b[2 * p + 1][0], b[2 * p + 1][1],
                       bBase[p] + bo + ((u ^ bMask[p]) << 4));
            }
#pragma unroll
            for (int mi = 0; mi < 4; mi++)
#pragma unroll
                for (int ni = 0; ni < 4; ni++)
                    mma_bf16(acc[mi][ni], a[mi], b[ni]);
        }
        buf = (buf + 1) % 3;
    }

    // ---- epilogue ----
    const int rbase = bm * 128 + wm + (lane >> 2);
    const int cbase = bn * 128 + wn + (lane & 3) * 2;
    const bool fused = (!fp32_only) && (blockIdx.z < 2);
    if (fused) {
        __nv_bfloat16* Oh = (blockIdx.z == 0) ? H0 : H1;
        __nv_bfloat16* Ol = (blockIdx.z == 0) ? L0 : L1;
#pragma unroll
        for (int mi = 0; mi < 4; mi++) {
#pragma unroll
            for (int ni = 0; ni < 4; ni++) {
                const int col = cbase + ni * 8;
                const int h = col >> 6, d = col & 63;
#pragma unroll
                for (int half = 0; half < 2; half++) {
                    const int m = rbase + mi * 16 + half * 8;
                    const float a0 = acc[mi][ni][half * 2 + 0];
                    const float a1 = acc[mi][ni][half * 2 + 1];
                    const uint32_t hi2 = packbf2(a0, a1);
                    const uint32_t lo2 = packbf2(a0 - bf16rt(a0), a1 - bf16rt(a1));
                    const int bh = (m >> 11) * NHEAD + h;
                    const size_t dst = ((size_t)bh * S_LEN + (m & 2047)) * HDIM + d;
                    *(uint32_t*)(Oh + dst) = hi2;
                    *(uint32_t*)(Ol + dst) = lo2;
                }
            }
        }
    } else {
#pragma unroll
        for (int mi = 0; mi < 4; mi++) {
#pragma unroll
            for (int ni = 0; ni < 4; ni++) {
                const int col = cbase + ni * 8;
                float b0 = 0.0f, b1 = 0.0f;
                if (bias != nullptr) { b0 = bias[col]; b1 = bias[col + 1]; }
                float2 v01, v23;
                v01.x = acc[mi][ni][0] + b0; v01.y = acc[mi][ni][1] + b1;
                v23.x = acc[mi][ni][2] + b0; v23.y = acc[mi][ni][3] + b1;
                *(float2*)(Cf + (size_t)(rbase + mi * 16)     * DMODEL + col) = v01;
                *(float2*)(Cf + (size_t)(rbase + mi * 16 + 8) * DMODEL + col) = v23;
            }
        }
    }
}

// ---------------- HMMA flash attention (causal, unscaled, bf16 hi/lo 3-pass) ----
// grid (16, 32): CTA = 128 q-rows; 8 warps x 16 rows; k-tiles of 64; 96KB smem.
// Writes ctx directly as cbig [m][3072] = [hi | lo | hi].
__global__ __launch_bounds__(256, 2) void flash_mma(
    const __nv_bfloat16* __restrict__ Qh, const __nv_bfloat16* __restrict__ Ql,
    const __nv_bfloat16* __restrict__ Kh, const __nv_bfloat16* __restrict__ Kl,
    const __nv_bfloat16* __restrict__ Vth, const __nv_bfloat16* __restrict__ Vtl,
    __nv_bfloat16* __restrict__ Cbig)
{
    extern __shared__ __align__(1024) unsigned char dsm[];
    const int tid  = threadIdx.x;
    const int wid  = tid >> 5;
    const int lane = tid & 31;
    const int qt   = (int)gridDim.x - 1 - (int)blockIdx.x;   // big tiles first
    const int bh   = blockIdx.y;
    const int b    = bh >> 4, h = bh & 15;

    const uint32_t s0   = smem_u32(dsm);
    const uint32_t sQh  = (s0 + 1023) & ~1023u;
    const uint32_t sQl  = sQh + 16384;
    const uint32_t sStg = sQh + 32768;          // 2 x 32768

    // ---- load Q tile (128 rows x 128B) hi+lo, swizzled ----
    {
        const __nv_bfloat16* qh = Qh + ((size_t)bh * S_LEN + qt * 128) * HDIM;
        const __nv_bfloat16* ql = Ql + ((size_t)bh * S_LEN + qt * 128) * HDIM;
#pragma unroll
        for (int i = 0; i < 4; i++) {
            int u   = tid + i * 256;
            int row = u >> 3, seg = u & 7;
            uint32_t off = row * 128 + (((uint32_t)(seg ^ (row & 7))) << 4);
            *(uint4*)(dsm + (sQh - s0) + off) = *(const uint4*)(qh + (size_t)row * HDIM + seg * 8);
            *(uint4*)(dsm + (sQl - s0) + off) = *(const uint4*)(ql + (size_t)row * HDIM + seg * 8);
        }
    }

    // ---- producer: K/V tile prefetch ----
    const int prow = tid >> 3;
    const int pseg = tid & 7;
    const uint32_t psw = ((uint32_t)(pseg ^ (prow & 7))) << 4;
    auto prefetch = [&](int kt, int bufi) {
        const uint32_t so = sStg + (uint32_t)bufi * 32768;
        const __nv_bfloat16* khG = Kh  + ((size_t)bh * S_LEN + kt * 64) * HDIM;
        const __nv_bfloat16* klG = Kl  + ((size_t)bh * S_LEN + kt * 64) * HDIM;
        const __nv_bfloat16* vhG = Vth + ((size_t)bh * HDIM) * S_LEN + kt * 64;
        const __nv_bfloat16* vlG = Vtl + ((size_t)bh * HDIM) * S_LEN + kt * 64;
#pragma unroll
        for (int i = 0; i < 2; i++) {
            int row = prow + i * 32;
            uint32_t off = row * 128 + psw;
            cp_async16(so +     0 + off, khG + (size_t)row * HDIM  + pseg * 8);
            cp_async16(so +  8192 + off, klG + (size_t)row * HDIM  + pseg * 8);
            cp_async16(so + 16384 + off, vhG + (size_t)row * S_LEN + pseg * 8);
            cp_async16(so + 24576 + off, vlG + (size_t)row * S_LEN + pseg * 8);
        }
        cp_commit();
    };

    // ---- consumer addressing ----
    const int qrow      = wid * 16 + (lane & 15);
    const uint32_t qOff = (uint32_t)qrow * 128;
    const uint32_t qMsk = qrow & 7;
    const uint32_t kselA = lane >> 4;
    // B: ldm_x4 pairs over row pairs (np covers rows np*16..+15)
    uint32_t bOff[4], bMsk[4];
#pragma unroll
    for (int np = 0; np < 4; np++) {
        int r = np * 16 + ((lane >> 4) << 3) + (lane & 7);
        bOff[np] = (uint32_t)r * 128;
        bMsk[np] = r & 7;
    }
    const uint32_t kaddB = (lane >> 3) & 1;

    float o[8][4];
#pragma unroll
    for (int n = 0; n < 8; n++)
#pragma unroll
        for (int r = 0; r < 4; r++) o[n][r] = 0.0f;
    float m0 = -1.0e30f, m1 = -1.0e30f, l0 = 0.0f, l1 = 0.0f;

    const int ktn = 2 * qt + 2;
    prefetch(0, 0);
    int buf = 0;
    for (int kt = 0; kt < ktn; kt++) {
        cp_wait0();
        __syncthreads();
        if (kt + 1 < ktn) prefetch(kt + 1, buf ^ 1);
        const uint32_t so = sStg + (uint32_t)buf * 32768;
        buf ^= 1;

        if (kt * 64 > qt * 128 + wid * 16 + 15) continue;   // fully masked for warp

        // ---- S = Q K^T (3-pass hi/lo) ----
        float s[8][4];
#pragma unroll
        for (int n = 0; n < 8; n++)
#pragma unroll
            for (int r = 0; r < 4; r++) s[n][r] = 0.0f;
#pragma unroll
        for (int ks = 0; ks < 4; ks++) {
            uint32_t aH[4], aL[4];
            uint32_t ua = (uint32_t)(ks * 2) + kselA;
            ldm_x4(aH[0], aH[1], aH[2], aH[3], sQh + qOff + ((ua ^ qMsk) << 4));
            ldm_x4(aL[0], aL[1], aL[2], aL[3], sQl + qOff + ((ua ^ qMsk) << 4));
            uint32_t ub = (uint32_t)(ks * 2) + kaddB;
#pragma unroll
            for (int np = 0; np < 4; np++) {
                uint32_t bh2[2][2], bl2[2][2];
                uint32_t off = bOff[np] + ((ub ^ bMsk[np]) << 4);
                ldm_x4(bh2[0][0], bh2[0][1], bh2[1][0], bh2[1][1], so + 0    + off);
                ldm_x4(bl2[0][0], bl2[0][1], bl2[1][0], bl2[1][1], so + 8192 + off);
#pragma unroll
                for (int u = 0; u < 2; u++) {
                    mma_bf16(s[2 * np + u], aH, bh2[u]);
                    mma_bf16(s[2 * np + u], aL, bh2[u]);
                    mma_bf16(s[2 * np + u], aH, bl2[u]);
                }
            }
        }

        // ---- causal mask ----
        const int rg0 = qt * 128 + wid * 16 + (lane >> 2);
        if (kt * 64 + 63 > rg0) {
#pragma unroll
            for (int n = 0; n < 8; n++) {
                int cg = kt * 64 + n * 8 + (lane & 3) * 2;
                if (cg     > rg0)     s[n][0] = -1.0e30f;
                if (cg + 1 > rg0)     s[n][1] = -1.0e30f;
                if (cg     > rg0 + 8) s[n][2] = -1.0e30f;
                if (cg + 1 > rg0 + 8) s[n][3] = -1.0e30f;
            }
        }

        // ---- online softmax ----
        float mx0 = -1.0e30f, mx1 = -1.0e30f;
#pragma unroll
        for (int n = 0; n < 8; n++) {
            mx0 = fmaxf(mx0, fmaxf(s[n][0], s[n][1]));
            mx1 = fmaxf(mx1, fmaxf(s[n][2], s[n][3]));
        }
        mx0 = fmaxf(mx0, __shfl_xor_sync(0xffffffffu, mx0, 1));
        mx0 = fmaxf(mx0, __shfl_xor_sync(0xffffffffu, mx0, 2));
        mx1 = fmaxf(mx1, __shfl_xor_sync(0xffffffffu, mx1, 1));
        mx1 = fmaxf(mx1, __shfl_xor_sync(0xffffffffu, mx1, 2));
        const float mn0 = fmaxf(m0, mx0), mn1 = fmaxf(m1, mx1);
        const float sc0 = __expf(m0 - mn0), sc1 = __expf(m1 - mn1);
        float rs0 = 0.0f, rs1 = 0.0f;
#pragma unroll
        for (int n = 0; n < 8; n++) {
            s[n][0] = __expf(s[n][0] - mn0);
            s[n][1] = __expf(s[n][1] - mn0);
            s[n][2] = __expf(s[n][2] - mn1);
            s[n][3] = __expf(s[n][3] - mn1);
            rs0 += s[n][0] + s[n][1];
            rs1 += s[n][2] + s[n][3];
        }
        rs0 += __shfl_xor_sync(0xffffffffu, rs0, 1);
        rs0 += __shfl_xor_sync(0xffffffffu, rs0, 2);
        rs1 += __shfl_xor_sync(0xffffffffu, rs1, 1);
        rs1 += __shfl_xor_sync(0xffffffffu, rs1, 2);
        m0 = mn0; m1 = mn1;
        l0 = l0 * sc0 + rs0; l1 = l1 * sc1 + rs1;
#pragma unroll
        for (int n = 0; n < 8; n++) {
            o[n][0] *= sc0; o[n][1] *= sc0;
            o[n][2] *= sc1; o[n][3] *= sc1;
        }

        // ---- P fragments (hi + lo), FA2 accumulator->A mapping ----
        uint32_t pH[4][4], pL[4][4];
#pragma unroll
        for (int f = 0; f < 4; f++) {
            const int n0i = 2 * f, n1i = 2 * f + 1;
            pH[f][0] = packbf2(s[n0i][0], s[n0i][1]);
            pH[f][1] = packbf2(s[n0i][2], s[n0i][3]);
            pH[f][2] = packbf2(s[n1i][0], s[n1i][1]);
            pH[f][3] = packbf2(s[n1i][2], s[n1i][3]);
            pL[f][0] = packbf2(s[n0i][0] - bf16rt(s[n0i][0]), s[n0i][1] - bf16rt(s[n0i][1]));
            pL[f][1] = packbf2(s[n0i][2] - bf16rt(s[n0i][2]), s[n0i][3] - bf16rt(s[n0i][3]));
            pL[f][2] = packbf2(s[n1i][0] - bf16rt(s[n1i][0]), s[n1i][1] - bf16rt(s[n1i][1]));
            pL[f][3] = packbf2(s[n1i][2] - bf16rt(s[n1i][2]), s[n1i][3] - bf16rt(s[n1i][3]));
        }

        // ---- O += P V (3-pass) ----
#pragma unroll
        for (int f = 0; f < 4; f++) {
            uint32_t ub = (uint32_t)(f * 2) + kaddB;
#pragma unroll
            for (int np = 0; np < 4; np++) {
                uint32_t bvh[2][2], bvl[2][2];
                uint32_t off = bOff[np] + ((ub ^ bMsk[np]) << 4);
                ldm_x4(bvh[0][0], bvh[0][1], bvh[1][0], bvh[1][1], so + 16384 + off);
                ldm_x4(bvl[0][0], bvl[0][1], bvl[1][0], bvl[1][1], so + 24576 + off);
#pragma unroll
                for (int u = 0; u < 2; u++) {
                    mma_bf16(o[2 * np + u], pH[f], bvh[u]);
                    mma_bf16(o[2 * np + u], pL[f], bvh[u]);
                    mma_bf16(o[2 * np + u], pH[f], bvl[u]);
                }
            }
        }
    }

    // ---- normalize + store directly as cbig [m][3072] = [hi|lo|hi] ----
    const float inv0 = 1.0f / l0, inv1 = 1.0f / l1;
    const int r0g = qt * 128 + wid * 16 + (lane >> 2);
    const size_t mrow0 = (size_t)(b * S_LEN) + r0g;
#pragma unroll
    for (int n = 0; n < 8; n++) {
        const int col = h * 64 + n * 8 + (lane & 3) * 2;
#pragma unroll
        for (int half = 0; half < 2; half++) {
            const float a0 = o[n][half * 2 + 0] * (half ? inv1 : inv0);
            const float a1 = o[n][half * 2 + 1] * (half ? inv1 : inv0);
            const uint32_t hi2 = packbf2(a0, a1);
            const uint32_t lo2 = packbf2(a0 - bf16rt(a0), a1 - bf16rt(a1));
            __nv_bfloat16* base = Cbig + (mrow0 + half * 8) * KBIG + col;
            *(uint32_t*)(base)              = hi2;
            *(uint32_t*)(base + DMODEL)     = lo2;
            *(uint32_t*)(base + 2 * DMODEL) = hi2;
        }
    }
}

// ---------------- launcher ----------------
extern "C" void kernel_launch(void* const* d_in, const int* in_sizes, int n_in,
                              void* d_out, int out_size)
{
    const float* X  = (const float*)d_in[0];
    const float* Wq = (const float*)d_in[1];
    const float* Wk = (const float*)d_in[2];
    const float* Wv = (const float*)d_in[3];
    const float* Wo = (const float*)d_in[4];
    const float* bo = (const float*)d_in[5];
    float* out = (float*)d_out;

    __nv_bfloat16 *xbig, *cbig, *wqb, *wkb, *wvb, *wob;
    __nv_bfloat16 *qh, *ql, *kh, *kl, *vth, *vtl;
    float *v;
    cudaGetSymbolAddress((void**)&xbig, g_xbig);
    cudaGetSymbolAddress((void**)&cbig, g_cbig);
    cudaGetSymbolAddress((void**)&wqb,  g_wqb);
    cudaGetSymbolAddress((void**)&wkb,  g_wkb);
    cudaGetSymbolAddress((void**)&wvb,  g_wvb);
    cudaGetSymbolAddress((void**)&wob,  g_wob);
    cudaGetSymbolAddress((void**)&v,    g_v);
    cudaGetSymbolAddress((void**)&qh,   g_qh);
    cudaGetSymbolAddress((void**)&ql,   g_ql);
    cudaGetSymbolAddress((void**)&kh,   g_kh);
    cudaGetSymbolAddress((void**)&kl,   g_kl);
    cudaGetSymbolAddress((void**)&vth,  g_vth);
    cudaGetSymbolAddress((void**)&vtl,  g_vtl);

    const int SMEM_GEMM = 3 * 32768 + 1024;     // 3-stage pipeline
    const int SMEM_FA   = 98304 + 1024;
    cudaFuncSetAttribute(gemm_mma, cudaFuncAttributeMaxDynamicSharedMemorySize, SMEM_GEMM);
    cudaFuncSetAttribute(flash_mma, cudaFuncAttributeMaxDynamicSharedMemorySize, SMEM_FA);

    // conversions
    cvt_x<<<MROWS * DMODEL / (256 * 4), 256>>>(X, xbig);
    dim3 wgrid(DMODEL / 32, DMODEL / 32);
    cvt_w<<<wgrid, dim3(32, 8)>>>(Wq, wqb);
    cvt_w<<<wgrid, dim3(32, 8)>>>(Wk, wkb);
    cvt_w<<<wgrid, dim3(32, 8)>>>(Wv, wvb);
    cvt_w<<<wgrid, dim3(32, 8)>>>(Wo, wob);

    // QKV projection: Q,K write bf16 head-split directly; V writes fp32
    gemm_mma<<<dim3(DMODEL / 128, MROWS / 128, 3), 256, SMEM_GEMM>>>(
        xbig, wqb, wkb, wvb, v, qh, ql, kh, kl, nullptr, 0);

    // V transpose + hi/lo split
    cvt_vt<<<dim3(S_LEN / 64, NBH), 256>>>(v, vth, vtl);

    // flash attention (HMMA), writes cbig directly
    flash_mma<<<dim3(S_LEN / 128, NBH), 256, SMEM_FA>>>(qh, ql, kh, kl, vth, vtl, cbig);

    // output projection (fp32 out + bias)
    gemm_mma<<<dim3(DMODEL / 128, MROWS / 128, 1), 256, SMEM_GEMM>>>(
        cbig, wob, wob, wob, out, nullptr, nullptr, nullptr, nullptr, bo, 1);
}

// round 12
// speedup vs baseline: 1.1134x; 1.1134x over previous
#include <cuda_runtime.h>
#include <cuda_bf16.h>
#include <stdint.h>
#include <math.h>

#define BATCH   2
#define S_LEN   2048
#define DMODEL  1024
#define NHEAD   16
#define HDIM    64
#define MROWS   (BATCH * S_LEN)   // 4096
#define KBIG    (3 * DMODEL)      // 3072: A=[hi|lo|hi], B=[hi|hi|lo]
#define KCH     (KBIG / 64)       // 48 chunks of K=64
#define NBH     (BATCH * NHEAD)   // 32

// ---------------- scratch (allocation-free device globals) ----------------
__device__ __align__(16) __nv_bfloat16 g_xbig[MROWS * KBIG];   // 24MB
__device__ __align__(16) __nv_bfloat16 g_cbig[MROWS * KBIG];   // 24MB
__device__ __align__(16) __nv_bfloat16 g_wqb[DMODEL * KBIG];
__device__ __align__(16) __nv_bfloat16 g_wkb[DMODEL * KBIG];
__device__ __align__(16) __nv_bfloat16 g_wvb[DMODEL * KBIG];
__device__ __align__(16) __nv_bfloat16 g_wob[DMODEL * KBIG];
__device__ float g_q[MROWS * DMODEL];
__device__ float g_k[MROWS * DMODEL];
__device__ float g_v[MROWS * DMODEL];
__device__ float g_ctx[MROWS * DMODEL];
// attention bf16 hi/lo operands
__device__ __align__(16) __nv_bfloat16 g_qh[NBH * S_LEN * HDIM];
__device__ __align__(16) __nv_bfloat16 g_ql[NBH * S_LEN * HDIM];
__device__ __align__(16) __nv_bfloat16 g_kh[NBH * S_LEN * HDIM];
__device__ __align__(16) __nv_bfloat16 g_kl[NBH * S_LEN * HDIM];
__device__ __align__(16) __nv_bfloat16 g_vth[NBH * HDIM * S_LEN];  // transposed
__device__ __align__(16) __nv_bfloat16 g_vtl[NBH * HDIM * S_LEN];

// ---------------- PTX helpers (all legal on plain sm_103) ----------------
__device__ __forceinline__ uint32_t smem_u32(const void* p) {
    uint32_t a;
    asm("{ .reg .u64 t; cvta.to.shared.u64 t, %1; cvt.u32.u64 %0, t; }" : "=r"(a) : "l"(p));
    return a;
}
__device__ __forceinline__ void cp_async16(uint32_t saddr, const void* gaddr) {
    asm volatile("cp.async.cg.shared.global [%0], [%1], 16;" :: "r"(saddr), "l"(gaddr));
}
__device__ __forceinline__ void cp_commit() {
    asm volatile("cp.async.commit_group;" ::: "memory");
}
__device__ __forceinline__ void cp_wait0() {
    asm volatile("cp.async.wait_group 0;" ::: "memory");
}
__device__ __forceinline__ void ldm_x4(uint32_t& r0, uint32_t& r1, uint32_t& r2, uint32_t& r3,
                                       uint32_t addr) {
    asm volatile("ldmatrix.sync.aligned.m8n8.x4.shared.b16 {%0,%1,%2,%3}, [%4];"
                 : "=r"(r0), "=r"(r1), "=r"(r2), "=r"(r3) : "r"(addr));
}
__device__ __forceinline__ void mma_bf16(float* d, const uint32_t* a, const uint32_t* b) {
    asm volatile(
        "mma.sync.aligned.m16n8k16.row.col.f32.bf16.bf16.f32 "
        "{%0,%1,%2,%3}, {%4,%5,%6,%7}, {%8,%9}, {%0,%1,%2,%3};"
        : "+f"(d[0]), "+f"(d[1]), "+f"(d[2]), "+f"(d[3])
        : "r"(a[0]), "r"(a[1]), "r"(a[2]), "r"(a[3]), "r"(b[0]), "r"(b[1]));
}
__device__ __forceinline__ uint32_t packbf2(float a, float b) {
    __nv_bfloat162 t = __floats2bfloat162_rn(a, b);
    return *reinterpret_cast<uint32_t*>(&t);
}
__device__ __forceinline__ float bf16rt(float v) {
    return __bfloat162float(__float2bfloat16(v));
}

// ---------------- conversion: fp32 -> bf16 hi/lo packed, K'=3072 ----------------
__global__ __launch_bounds__(256) void cvt_x(const float* __restrict__ X,
                                             __nv_bfloat16* __restrict__ O)
{
    int idx = blockIdx.x * 256 + threadIdx.x;
    int m   = idx >> 8;
    int k4  = (idx & 255) << 2;
    float4 v = *(const float4*)(X + (size_t)m * DMODEL + k4);
    float f[4] = {v.x, v.y, v.z, v.w};
    __nv_bfloat16 h[4], l[4];
#pragma unroll
    for (int i = 0; i < 4; i++) {
        h[i] = __float2bfloat16(f[i]);
        l[i] = __float2bfloat16(f[i] - __bfloat162float(h[i]));
    }
    __nv_bfloat162 h01, h23, l01, l23;
    h01.x = h[0]; h01.y = h[1]; h23.x = h[2]; h23.y = h[3];
    l01.x = l[0]; l01.y = l[1]; l23.x = l[2]; l23.y = l[3];
    __nv_bfloat162* p0 = (__nv_bfloat162*)(O + (size_t)m * KBIG + k4);
    __nv_bfloat162* p1 = (__nv_bfloat162*)(O + (size_t)m * KBIG + DMODEL + k4);
    __nv_bfloat162* p2 = (__nv_bfloat162*)(O + (size_t)m * KBIG + 2 * DMODEL + k4);
    p0[0] = h01; p0[1] = h23;      // hi
    p1[0] = l01; p1[1] = l23;      // lo
    p2[0] = h01; p2[1] = h23;      // hi
}

// all four weight conversions in one launch: z selects (W, O)
__global__ __launch_bounds__(256) void cvt_w4(
    const float* __restrict__ W0, const float* __restrict__ W1,
    const float* __restrict__ W2, const float* __restrict__ W3,
    __nv_bfloat16* O0, __nv_bfloat16* O1, __nv_bfloat16* O2, __nv_bfloat16* O3)
{
    const float* W = (blockIdx.z == 0) ? W0 : (blockIdx.z == 1) ? W1
                   : (blockIdx.z == 2) ? W2 : W3;
    __nv_bfloat16* O = (blockIdx.z == 0) ? O0 : (blockIdx.z == 1) ? O1
                     : (blockIdx.z == 2) ? O2 : O3;
    __shared__ float t[32][33];
    int n0 = blockIdx.x * 32, k0 = blockIdx.y * 32;
    int tx = threadIdx.x, ty = threadIdx.y;
#pragma unroll
    for (int i = 0; i < 4; i++)
        t[ty + 8 * i][tx] = W[(size_t)(k0 + ty + 8 * i) * DMODEL + n0 + tx];
    __syncthreads();
#pragma unroll
    for (int i = 0; i < 4; i++) {
        int n = n0 + ty + 8 * i, k = k0 + tx;
        float v = t[tx][ty + 8 * i];
        __nv_bfloat16 h = __float2bfloat16(v);
        __nv_bfloat16 l = __float2bfloat16(v - __bfloat162float(h));
        O[(size_t)n * KBIG + k]              = h;
        O[(size_t)n * KBIG + DMODEL + k]     = h;
        O[(size_t)n * KBIG + 2 * DMODEL + k] = l;
    }
}

// fp32 [b*S+s][h*64+d] -> bf16 hi/lo [bh][s][64]
__global__ __launch_bounds__(256) void cvt_head(const float* __restrict__ X,
                                                __nv_bfloat16* __restrict__ Oh,
                                                __nv_bfloat16* __restrict__ Ol)
{
    int idx = blockIdx.x * 256 + threadIdx.x;
    int m   = idx >> 8;
    int col = (idx & 255) << 2;
    int h   = col >> 6, d = col & 63;
    int b   = m >> 11, s = m & 2047;
    float4 v = *(const float4*)(X + (size_t)m * DMODEL + col);
    float f[4] = {v.x, v.y, v.z, v.w};
    __nv_bfloat16 hh[4], ll[4];
#pragma unroll
    for (int i = 0; i < 4; i++) {
        hh[i] = __float2bfloat16(f[i]);
        ll[i] = __float2bfloat16(f[i] - __bfloat162float(hh[i]));
    }
    size_t dst = ((size_t)(b * NHEAD + h) * S_LEN + s) * HDIM + d;
    __nv_bfloat162 a, c;
    a.x = hh[0]; a.y = hh[1]; c.x = hh[2]; c.y = hh[3];
    ((__nv_bfloat162*)(Oh + dst))[0] = a; ((__nv_bfloat162*)(Oh + dst))[1] = c;
    a.x = ll[0]; a.y = ll[1]; c.x = ll[2]; c.y = ll[3];
    ((__nv_bfloat162*)(Ol + dst))[0] = a; ((__nv_bfloat162*)(Ol + dst))[1] = c;
}

// V fp32 [b*S+s][h*64+d] -> transposed bf16 hi/lo [bh][d][s]
__global__ __launch_bounds__(256) void cvt_vt(const float* __restrict__ V,
                                              __nv_bfloat16* __restrict__ Oh,
                                              __nv_bfloat16* __restrict__ Ol)
{
    __shared__ float t[64][65];
    const int tid = threadIdx.x;
    const int s0  = blockIdx.x * 64;
    const int bh  = blockIdx.y;
    const int b   = bh >> 4, h = bh & 15;
#pragma unroll
    for (int i = 0; i < 16; i++) {
        int u = tid + i * 256;
        int s = u >> 6, d = u & 63;
        t[s][d] = V[((size_t)(b * S_LEN) + s0 + s) * DMODEL + h * 64 + d];
    }
    __syncthreads();
    const int d  = tid >> 2;
    const int jg = tid & 3;
    __nv_bfloat16 hv[16], lv[16];
#pragma unroll
    for (int jj = 0; jj < 16; jj++) {
        float v = t[jg * 16 + jj][d];
        hv[jj] = __float2bfloat16(v);
        lv[jj] = __float2bfloat16(v - __bfloat162float(hv[jj]));
    }
    size_t dst = ((size_t)bh * HDIM + d) * S_LEN + s0 + jg * 16;
    ((uint4*)(Oh + dst))[0] = ((uint4*)hv)[0];
    ((uint4*)(Oh + dst))[1] = ((uint4*)hv)[1];
    ((uint4*)(Ol + dst))[0] = ((uint4*)lv)[0];
    ((uint4*)(Ol + dst))[1] = ((uint4*)lv)[1];
}

// ---------------- bf16 HMMA GEMM (R8/R9 structure, merged B ldmatrix) --------
// CTA 128x128, K chunk 64, 2-stage cp.async, 8 warps (64x32 warp tile).
__global__ __launch_bounds__(256) void gemm_mma(
    const __nv_bfloat16* __restrict__ A,
    const __nv_bfloat16* __restrict__ B0, const __nv_bfloat16* __restrict__ B1,
    const __nv_bfloat16* __restrict__ B2,
    float* C0, float* C1, float* C2,
    const float* __restrict__ bias)
{
    extern __shared__ __align__(1024) unsigned char dsm[];

    const __nv_bfloat16* Bt = (blockIdx.z == 0) ? B0 : (blockIdx.z == 1) ? B1 : B2;
    float* C                = (blockIdx.z == 0) ? C0 : (blockIdx.z == 1) ? C1 : C2;

    const int tid  = threadIdx.x;
    const int wid  = tid >> 5;
    const int lane = tid & 31;
    const int bm   = blockIdx.y, bn = blockIdx.x;
    const int wm   = (wid & 1) * 64;
    const int wn   = (wid >> 1) * 32;

    const uint32_t s0 = smem_u32(dsm);
    const uint32_t sA = (s0 + 1023) & ~1023u;
    const uint32_t sB = sA + 32768;

    const int row0 = tid >> 3;
    const int seg  = tid & 7;
    const uint32_t swz = (uint32_t)((seg ^ (row0 & 7)) << 4);
    const __nv_bfloat16* aG = A  + (size_t)(bm * 128 + row0) * KBIG + seg * 8;
    const __nv_bfloat16* bG = Bt + (size_t)(bn * 128 + row0) * KBIG + seg * 8;
    const uint32_t stA = sA + row0 * 128 + swz;
    const uint32_t stB = sB + row0 * 128 + swz;

    uint32_t aBase[4], aMask[4];
#pragma unroll
    for (int mi = 0; mi < 4; mi++) {
        int r = wm + mi * 16 + (lane & 15);
        aBase[mi] = sA + r * 128;
        aMask[mi] = r & 7;
    }
    // B: merged ldm_x4; pair p covers cols wn+p*16 .. +15 (verified R10)
    uint32_t bBase[2], bMask[2];
#pragma unroll
    for (int p = 0; p < 2; p++) {
        int r = wn + p * 16 + ((lane >> 4) << 3) + (lane & 7);
        bBase[p] = sB + r * 128;
        bMask[p] = r & 7;
    }
    const uint32_t kselA = (lane >> 4);
    const uint32_t kaddB = (lane >> 3) & 1;

    float acc[4][4][4];
#pragma unroll
    for (int mi = 0; mi < 4; mi++)
#pragma unroll
        for (int ni = 0; ni < 4; ni++)
#pragma unroll
            for (int r = 0; r < 4; r++) acc[mi][ni][r] = 0.0f;

    auto load_chunk = [&](int c, int buf) {
        const uint32_t bo = (uint32_t)buf * 16384;
        const __nv_bfloat16* ap = aG + c * 64;
        const __nv_bfloat16* bp = bG + c * 64;
#pragma unroll
        for (int i = 0; i < 4; i++) {
            cp_async16(stA + bo + i * 4096, ap + (size_t)i * 32 * KBIG);
            cp_async16(stB + bo + i * 4096, bp + (size_t)i * 32 * KBIG);
        }
        cp_commit();
    };

    load_chunk(0, 0);
    int buf = 0;
    for (int c = 0; c < KCH; c++) {
        cp_wait0();
        __syncthreads();
        if (c + 1 < KCH) load_chunk(c + 1, buf ^ 1);
        const uint32_t bo = (uint32_t)buf * 16384;
#pragma unroll
        for (int ks = 0; ks < 4; ks++) {
            uint32_t a[4][4], b[4][2];
#pragma unroll
            for (int mi = 0; mi < 4; mi++) {
                uint32_t u = (uint32_t)(ks * 2) + kselA;
                ldm_x4(a[mi][0], a[mi][1], a[mi][2], a[mi][3],
                       aBase[mi] + bo + ((u ^ aMask[mi]) << 4));
            }
#pragma unroll
            for (int p = 0; p < 2; p++) {
                uint32_t u = (uint32_t)(ks * 2) + kaddB;
                ldm_x4(b[2 * p][0], b[2 * p][1], b[2 * p + 1][0], b[2 * p + 1][1],
                       bBase[p] + bo + ((u ^ bMask[p]) << 4));
            }
#pragma unroll
            for (int mi = 0; mi < 4; mi++)
#pragma unroll
                for (int ni = 0; ni < 4; ni++)
                    mma_bf16(acc[mi][ni], a[mi], b[ni]);
        }
        buf ^= 1;
    }

    const int rbase = bm * 128 + wm + (lane >> 2);
    const int cbase = bn * 128 + wn + (lane & 3) * 2;
#pragma unroll
    for (int mi = 0; mi < 4; mi++) {
#pragma unroll
        for (int ni = 0; ni < 4; ni++) {
            const int col = cbase + ni * 8;
            float b0 = 0.0f, b1 = 0.0f;
            if (bias != nullptr) { b0 = bias[col]; b1 = bias[col + 1]; }
            float2 v01, v23;
            v01.x = acc[mi][ni][0] + b0; v01.y = acc[mi][ni][1] + b1;
            v23.x = acc[mi][ni][2] + b0; v23.y = acc[mi][ni][3] + b1;
            *(float2*)(C + (size_t)(rbase + mi * 16)     * DMODEL + col) = v01;
            *(float2*)(C + (size_t)(rbase + mi * 16 + 8) * DMODEL + col) = v23;
        }
    }
}

// ---------------- HMMA flash attention (R9 structure, merged B ldmatrix) -----
// grid (16, 32): CTA = 128 q-rows; 8 warps x 16 rows; k-tiles of 64; 96KB smem.
__global__ __launch_bounds__(256, 2) void flash_mma(
    const __nv_bfloat16* __restrict__ Qh, const __nv_bfloat16* __restrict__ Ql,
    const __nv_bfloat16* __restrict__ Kh, const __nv_bfloat16* __restrict__ Kl,
    const __nv_bfloat16* __restrict__ Vth, const __nv_bfloat16* __restrict__ Vtl,
    float* __restrict__ Ctx)
{
    extern __shared__ __align__(1024) unsigned char dsm[];
    const int tid  = threadIdx.x;
    const int wid  = tid >> 5;
    const int lane = tid & 31;
    const int qt   = (int)gridDim.x - 1 - (int)blockIdx.x;   // big tiles first
    const int bh   = blockIdx.y;
    const int b    = bh >> 4, h = bh & 15;

    const uint32_t s0   = smem_u32(dsm);
    const uint32_t sQh  = (s0 + 1023) & ~1023u;
    const uint32_t sQl  = sQh + 16384;
    const uint32_t sStg = sQh + 32768;          // 2 x 32768

    // ---- load Q tile (128 rows x 128B) hi+lo, swizzled ----
    {
        const __nv_bfloat16* qh = Qh + ((size_t)bh * S_LEN + qt * 128) * HDIM;
        const __nv_bfloat16* ql = Ql + ((size_t)bh * S_LEN + qt * 128) * HDIM;
#pragma unroll
        for (int i = 0; i < 4; i++) {
            int u   = tid + i * 256;
            int row = u >> 3, seg = u & 7;
            uint32_t off = row * 128 + (((uint32_t)(seg ^ (row & 7))) << 4);
            *(uint4*)(dsm + (sQh - s0) + off) = *(const uint4*)(qh + (size_t)row * HDIM + seg * 8);
            *(uint4*)(dsm + (sQl - s0) + off) = *(const uint4*)(ql + (size_t)row * HDIM + seg * 8);
        }
    }

    // ---- producer: K/V tile prefetch ----
    const int prow = tid >> 3;
    const int pseg = tid & 7;
    const uint32_t psw = ((uint32_t)(pseg ^ (prow & 7))) << 4;
    auto prefetch = [&](int kt, int bufi) {
        const uint32_t so = sStg + (uint32_t)bufi * 32768;
        const __nv_bfloat16* khG = Kh  + ((size_t)bh * S_LEN + kt * 64) * HDIM;
        const __nv_bfloat16* klG = Kl  + ((size_t)bh * S_LEN + kt * 64) * HDIM;
        const __nv_bfloat16* vhG = Vth + ((size_t)bh * HDIM) * S_LEN + kt * 64;
        const __nv_bfloat16* vlG = Vtl + ((size_t)bh * HDIM) * S_LEN + kt * 64;
#pragma unroll
        for (int i = 0; i < 2; i++) {
            int row = prow + i * 32;
            uint32_t off = row * 128 + psw;
            cp_async16(so +     0 + off, khG + (size_t)row * HDIM  + pseg * 8);
            cp_async16(so +  8192 + off, klG + (size_t)row * HDIM  + pseg * 8);
            cp_async16(so + 16384 + off, vhG + (size_t)row * S_LEN + pseg * 8);
            cp_async16(so + 24576 + off, vlG + (size_t)row * S_LEN + pseg * 8);
        }
        cp_commit();
    };

    // ---- consumer addressing ----
    const int qrow      = wid * 16 + (lane & 15);
    const uint32_t qOff = (uint32_t)qrow * 128;
    const uint32_t qMsk = qrow & 7;
    const uint32_t kselA = lane >> 4;
    // B: merged ldm_x4 over row pairs (np covers rows np*16..+15, verified R10)
    uint32_t bOff[4], bMsk[4];
#pragma unroll
    for (int np = 0; np < 4; np++) {
        int r = np * 16 + ((lane >> 4) << 3) + (lane & 7);
        bOff[np] = (uint32_t)r * 128;
        bMsk[np] = r & 7;
    }
    const uint32_t kaddB = (lane >> 3) & 1;

    float o[8][4];
#pragma unroll
    for (int n = 0; n < 8; n++)
#pragma unroll
        for (int r = 0; r < 4; r++) o[n][r] = 0.0f;
    float m0 = -1.0e30f, m1 = -1.0e30f, l0 = 0.0f, l1 = 0.0f;

    const int ktn = 2 * qt + 2;
    prefetch(0, 0);
    int buf = 0;
    for (int kt = 0; kt < ktn; kt++) {
        cp_wait0();
        __syncthreads();
        if (kt + 1 < ktn) prefetch(kt + 1, buf ^ 1);
        const uint32_t so = sStg + (uint32_t)buf * 32768;
        buf ^= 1;

        if (kt * 64 > qt * 128 + wid * 16 + 15) continue;   // fully masked for warp

        // ---- S = Q K^T (3-pass hi/lo) ----
        float s[8][4];
#pragma unroll
        for (int n = 0; n < 8; n++)
#pragma unroll
            for (int r = 0; r < 4; r++) s[n][r] = 0.0f;
#pragma unroll
        for (int ks = 0; ks < 4; ks++) {
            uint32_t aH[4], aL[4];
            uint32_t ua = (uint32_t)(ks * 2) + kselA;
            ldm_x4(aH[0], aH[1], aH[2], aH[3], sQh + qOff + ((ua ^ qMsk) << 4));
            ldm_x4(aL[0], aL[1], aL[2], aL[3], sQl + qOff + ((ua ^ qMsk) << 4));
            uint32_t ub = (uint32_t)(ks * 2) + kaddB;
#pragma unroll
            for (int np = 0; np < 4; np++) {
                uint32_t bh2[2][2], bl2[2][2];
                uint32_t off = bOff[np] + ((ub ^ bMsk[np]) << 4);
                ldm_x4(bh2[0][0], bh2[0][1], bh2[1][0], bh2[1][1], so + 0    + off);
                ldm_x4(bl2[0][0], bl2[0][1], bl2[1][0], bl2[1][1], so + 8192 + off);
#pragma unroll
                for (int u = 0; u < 2; u++) {
                    mma_bf16(s[2 * np + u], aH, bh2[u]);
                    mma_bf16(s[2 * np + u], aL, bh2[u]);
                    mma_bf16(s[2 * np + u], aH, bl2[u]);
                }
            }
        }

        // ---- causal mask ----
        const int rg0 = qt * 128 + wid * 16 + (lane >> 2);
        if (kt * 64 + 63 > rg0) {
#pragma unroll
            for (int n = 0; n < 8; n++) {
                int cg = kt * 64 + n * 8 + (lane & 3) * 2;
                if (cg     > rg0)     s[n][0] = -1.0e30f;
                if (cg + 1 > rg0)     s[n][1] = -1.0e30f;
                if (cg     > rg0 + 8) s[n][2] = -1.0e30f;
                if (cg + 1 > rg0 + 8) s[n][3] = -1.0e30f;
            }
        }

        // ---- online softmax ----
        float mx0 = -1.0e30f, mx1 = -1.0e30f;
#pragma unroll
        for (int n = 0; n < 8; n++) {
            mx0 = fmaxf(mx0, fmaxf(s[n][0], s[n][1]));
            mx1 = fmaxf(mx1, fmaxf(s[n][2], s[n][3]));
        }
        mx0 = fmaxf(mx0, __shfl_xor_sync(0xffffffffu, mx0, 1));
        mx0 = fmaxf(mx0, __shfl_xor_sync(0xffffffffu, mx0, 2));
        mx1 = fmaxf(mx1, __shfl_xor_sync(0xffffffffu, mx1, 1));
        mx1 = fmaxf(mx1, __shfl_xor_sync(0xffffffffu, mx1, 2));
        const float mn0 = fmaxf(m0, mx0), mn1 = fmaxf(m1, mx1);
        const float sc0 = __expf(m0 - mn0), sc1 = __expf(m1 - mn1);
        float rs0 = 0.0f, rs1 = 0.0f;
#pragma unroll
        for (int n = 0; n < 8; n++) {
            s[n][0] = __expf(s[n][0] - mn0);
            s[n][1] = __expf(s[n][1] - mn0);
            s[n][2] = __expf(s[n][2] - mn1);
            s[n][3] = __expf(s[n][3] - mn1);
            rs0 += s[n][0] + s[n][1];
            rs1 += s[n][2] + s[n][3];
        }
        rs0 += __shfl_xor_sync(0xffffffffu, rs0, 1);
        rs0 += __shfl_xor_sync(0xffffffffu, rs0, 2);
        rs1 += __shfl_xor_sync(0xffffffffu, rs1, 1);
        rs1 += __shfl_xor_sync(0xffffffffu, rs1, 2);
        m0 = mn0; m1 = mn1;
        l0 = l0 * sc0 + rs0; l1 = l1 * sc1 + rs1;
#pragma unroll
        for (int n = 0; n < 8; n++) {
            o[n][0] *= sc0; o[n][1] *= sc0;
            o[n][2] *= sc1; o[n][3] *= sc1;
        }

        // ---- P fragments (hi + lo), FA2 accumulator->A mapping ----
        uint32_t pH[4][4], pL[4][4];
#pragma unroll
        for (int f = 0; f < 4; f++) {
            const int n0i = 2 * f, n1i = 2 * f + 1;
            pH[f][0] = packbf2(s[n0i][0], s[n0i][1]);
            pH[f][1] = packbf2(s[n0i][2], s[n0i][3]);
            pH[f][2] = packbf2(s[n1i][0], s[n1i][1]);
            pH[f][3] = packbf2(s[n1i][2], s[n1i][3]);
            pL[f][0] = packbf2(s[n0i][0] - bf16rt(s[n0i][0]), s[n0i][1] - bf16rt(s[n0i][1]));
            pL[f][1] = packbf2(s[n0i][2] - bf16rt(s[n0i][2]), s[n0i][3] - bf16rt(s[n0i][3]));
            pL[f][2] = packbf2(s[n1i][0] - bf16rt(s[n1i][0]), s[n1i][1] - bf16rt(s[n1i][1]));
            pL[f][3] = packbf2(s[n1i][2] - bf16rt(s[n1i][2]), s[n1i][3] - bf16rt(s[n1i][3]));
        }

        // ---- O += P V (3-pass) ----
#pragma unroll
        for (int f = 0; f < 4; f++) {
            uint32_t ub = (uint32_t)(f * 2) + kaddB;
#pragma unroll
            for (int np = 0; np < 4; np++) {
                uint32_t bvh[2][2], bvl[2][2];
                uint32_t off = bOff[np] + ((ub ^ bMsk[np]) << 4);
                ldm_x4(bvh[0][0], bvh[0][1], bvh[1][0], bvh[1][1], so + 16384 + off);
                ldm_x4(bvl[0][0], bvl[0][1], bvl[1][0], bvl[1][1], so + 24576 + off);
#pragma unroll
                for (int u = 0; u < 2; u++) {
                    mma_bf16(o[2 * np + u], pH[f], bvh[u]);
                    mma_bf16(o[2 * np + u], pL[f], bvh[u]);
                    mma_bf16(o[2 * np + u], pH[f], bvl[u]);
                }
            }
        }
    }

    // ---- normalize + store ctx fp32 [b*S+s][h*64+c] ----
    const float inv0 = 1.0f / l0, inv1 = 1.0f / l1;
    const int r0g = qt * 128 + wid * 16 + (lane >> 2);
#pragma unroll
    for (int n = 0; n < 8; n++) {
        const int col = h * 64 + n * 8 + (lane & 3) * 2;
        float2 v01, v23;
        v01.x = o[n][0] * inv0; v01.y = o[n][1] * inv0;
        v23.x = o[n][2] * inv1; v23.y = o[n][3] * inv1;
        *(float2*)(Ctx + ((size_t)(b * S_LEN) + r0g)     * DMODEL + col) = v01;
        *(float2*)(Ctx + ((size_t)(b * S_LEN) + r0g + 8) * DMODEL + col) = v23;
    }
}

// ---------------- launcher ----------------
extern "C" void kernel_launch(void* const* d_in, const int* in_sizes, int n_in,
                              void* d_out, int out_size)
{
    const float* X  = (const float*)d_in[0];
    const float* Wq = (const float*)d_in[1];
    const float* Wk = (const float*)d_in[2];
    const float* Wv = (const float*)d_in[3];
    const float* Wo = (const float*)d_in[4];
    const float* bo = (const float*)d_in[5];
    float* out = (float*)d_out;

    __nv_bfloat16 *xbig, *cbig, *wqb, *wkb, *wvb, *wob;
    __nv_bfloat16 *qh, *ql, *kh, *kl, *vth, *vtl;
    float *q, *k, *v, *ctx;
    cudaGetSymbolAddress((void**)&xbig, g_xbig);
    cudaGetSymbolAddress((void**)&cbig, g_cbig);
    cudaGetSymbolAddress((void**)&wqb,  g_wqb);
    cudaGetSymbolAddress((void**)&wkb,  g_wkb);
    cudaGetSymbolAddress((void**)&wvb,  g_wvb);
    cudaGetSymbolAddress((void**)&wob,  g_wob);
    cudaGetSymbolAddress((void**)&q,    g_q);
    cudaGetSymbolAddress((void**)&k,    g_k);
    cudaGetSymbolAddress((void**)&v,    g_v);
    cudaGetSymbolAddress((void**)&ctx,  g_ctx);
    cudaGetSymbolAddress((void**)&qh,   g_qh);
    cudaGetSymbolAddress((void**)&ql,   g_ql);
    cudaGetSymbolAddress((void**)&kh,   g_kh);
    cudaGetSymbolAddress((void**)&kl,   g_kl);
    cudaGetSymbolAddress((void**)&vth,  g_vth);
    cudaGetSymbolAddress((void**)&vtl,  g_vtl);

    const int SMEM_GEMM = 65536 + 1024;
    const int SMEM_FA   = 98304 + 1024;
    cudaFuncSetAttribute(gemm_mma, cudaFuncAttributeMaxDynamicSharedMemorySize, SMEM_GEMM);
    cudaFuncSetAttribute(flash_mma, cudaFuncAttributeMaxDynamicSharedMemorySize, SMEM_FA);

    // conversions
    cvt_x<<<MROWS * DMODEL / (256 * 4), 256>>>(X, xbig);
    cvt_w4<<<dim3(DMODEL / 32, DMODEL / 32, 4), dim3(32, 8)>>>(
        Wq, Wk, Wv, Wo, wqb, wkb, wvb, wob);

    // QKV projection (HMMA)
    gemm_mma<<<dim3(DMODEL / 128, MROWS / 128, 3), 256, SMEM_GEMM>>>(
        xbig, wqb, wkb, wvb, q, k, v, nullptr);

    // attention operand prep
    const int cg = MROWS * DMODEL / (256 * 4);
    cvt_head<<<cg, 256>>>(q, qh, ql);
    cvt_head<<<cg, 256>>>(k, kh, kl);
    cvt_vt<<<dim3(S_LEN / 64, NBH), 256>>>(v, vth, vtl);

    // flash attention (HMMA)
    flash_mma<<<dim3(S_LEN / 128, NBH), 256, SMEM_FA>>>(qh, ql, kh, kl, vth, vtl, ctx);

    // output projection
    cvt_x<<<MROWS * DMODEL / (256 * 4), 256>>>(ctx, cbig);
    gemm_mma<<<dim3(DMODEL / 128, MROWS / 128, 1), 256, SMEM_GEMM>>>(
        cbig, wob, wob, wob, out, nullptr, nullptr, bo);
}

// round 13
// speedup vs baseline: 1.1659x; 1.0472x over previous
#include <cuda_runtime.h>
#include <cuda_bf16.h>
#include <stdint.h>
#include <math.h>

#define BATCH   2
#define S_LEN   2048
#define DMODEL  1024
#define NHEAD   16
#define HDIM    64
#define MROWS   (BATCH * S_LEN)   // 4096
#define KBIG    (3 * DMODEL)      // 3072: A=[hi|lo|hi], B=[hi|hi|lo]
#define KCH     (KBIG / 64)       // 48 chunks of K=64
#define NBH     (BATCH * NHEAD)   // 32

// ---------------- scratch (allocation-free device globals) ----------------
__device__ __align__(16) __nv_bfloat16 g_xbig[MROWS * KBIG];   // 24MB
__device__ __align__(16) __nv_bfloat16 g_cbig[MROWS * KBIG];   // 24MB
__device__ __align__(16) __nv_bfloat16 g_wqb[DMODEL * KBIG];
__device__ __align__(16) __nv_bfloat16 g_wkb[DMODEL * KBIG];
__device__ __align__(16) __nv_bfloat16 g_wvb[DMODEL * KBIG];
__device__ __align__(16) __nv_bfloat16 g_wob[DMODEL * KBIG];
__device__ float g_v[MROWS * DMODEL];
// attention bf16 hi/lo operands
__device__ __align__(16) __nv_bfloat16 g_qh[NBH * S_LEN * HDIM];
__device__ __align__(16) __nv_bfloat16 g_ql[NBH * S_LEN * HDIM];
__device__ __align__(16) __nv_bfloat16 g_kh[NBH * S_LEN * HDIM];
__device__ __align__(16) __nv_bfloat16 g_kl[NBH * S_LEN * HDIM];
__device__ __align__(16) __nv_bfloat16 g_vth[NBH * HDIM * S_LEN];  // transposed
__device__ __align__(16) __nv_bfloat16 g_vtl[NBH * HDIM * S_LEN];

// ---------------- PTX helpers (all legal on plain sm_103) ----------------
__device__ __forceinline__ uint32_t smem_u32(const void* p) {
    uint32_t a;
    asm("{ .reg .u64 t; cvta.to.shared.u64 t, %1; cvt.u32.u64 %0, t; }" : "=r"(a) : "l"(p));
    return a;
}
__device__ __forceinline__ void cp_async16(uint32_t saddr, const void* gaddr) {
    asm volatile("cp.async.cg.shared.global [%0], [%1], 16;" :: "r"(saddr), "l"(gaddr));
}
__device__ __forceinline__ void cp_commit() {
    asm volatile("cp.async.commit_group;" ::: "memory");
}
__device__ __forceinline__ void cp_wait0() {
    asm volatile("cp.async.wait_group 0;" ::: "memory");
}
__device__ __forceinline__ void ldm_x4(uint32_t& r0, uint32_t& r1, uint32_t& r2, uint32_t& r3,
                                       uint32_t addr) {
    asm volatile("ldmatrix.sync.aligned.m8n8.x4.shared.b16 {%0,%1,%2,%3}, [%4];"
                 : "=r"(r0), "=r"(r1), "=r"(r2), "=r"(r3) : "r"(addr));
}
__device__ __forceinline__ void mma_bf16(float* d, const uint32_t* a, const uint32_t* b) {
    asm volatile(
        "mma.sync.aligned.m16n8k16.row.col.f32.bf16.bf16.f32 "
        "{%0,%1,%2,%3}, {%4,%5,%6,%7}, {%8,%9}, {%0,%1,%2,%3};"
        : "+f"(d[0]), "+f"(d[1]), "+f"(d[2]), "+f"(d[3])
        : "r"(a[0]), "r"(a[1]), "r"(a[2]), "r"(a[3]), "r"(b[0]), "r"(b[1]));
}
__device__ __forceinline__ uint32_t packbf2(float a, float b) {
    __nv_bfloat162 t = __floats2bfloat162_rn(a, b);
    return *reinterpret_cast<uint32_t*>(&t);
}
__device__ __forceinline__ float bf16rt(float v) {
    return __bfloat162float(__float2bfloat16(v));
}

// ---------------- conversion: fp32 -> bf16 hi/lo packed, K'=3072 ----------------
__global__ __launch_bounds__(256) void cvt_x(const float* __restrict__ X,
                                             __nv_bfloat16* __restrict__ O)
{
    int idx = blockIdx.x * 256 + threadIdx.x;
    int m   = idx >> 8;
    int k4  = (idx & 255) << 2;
    float4 v = *(const float4*)(X + (size_t)m * DMODEL + k4);
    float f[4] = {v.x, v.y, v.z, v.w};
    __nv_bfloat16 h[4], l[4];
#pragma unroll
    for (int i = 0; i < 4; i++) {
        h[i] = __float2bfloat16(f[i]);
        l[i] = __float2bfloat16(f[i] - __bfloat162float(h[i]));
    }
    __nv_bfloat162 h01, h23, l01, l23;
    h01.x = h[0]; h01.y = h[1]; h23.x = h[2]; h23.y = h[3];
    l01.x = l[0]; l01.y = l[1]; l23.x = l[2]; l23.y = l[3];
    __nv_bfloat162* p0 = (__nv_bfloat162*)(O + (size_t)m * KBIG + k4);
    __nv_bfloat162* p1 = (__nv_bfloat162*)(O + (size_t)m * KBIG + DMODEL + k4);
    __nv_bfloat162* p2 = (__nv_bfloat162*)(O + (size_t)m * KBIG + 2 * DMODEL + k4);
    p0[0] = h01; p0[1] = h23;      // hi
    p1[0] = l01; p1[1] = l23;      // lo
    p2[0] = h01; p2[1] = h23;      // hi
}

// all four weight conversions in one launch: z selects (W, O)
__global__ __launch_bounds__(256) void cvt_w4(
    const float* __restrict__ W0, const float* __restrict__ W1,
    const float* __restrict__ W2, const float* __restrict__ W3,
    __nv_bfloat16* O0, __nv_bfloat16* O1, __nv_bfloat16* O2, __nv_bfloat16* O3)
{
    const float* W = (blockIdx.z == 0) ? W0 : (blockIdx.z == 1) ? W1
                   : (blockIdx.z == 2) ? W2 : W3;
    __nv_bfloat16* O = (blockIdx.z == 0) ? O0 : (blockIdx.z == 1) ? O1
                     : (blockIdx.z == 2) ? O2 : O3;
    __shared__ float t[32][33];
    int n0 = blockIdx.x * 32, k0 = blockIdx.y * 32;
    int tx = threadIdx.x, ty = threadIdx.y;
#pragma unroll
    for (int i = 0; i < 4; i++)
        t[ty + 8 * i][tx] = W[(size_t)(k0 + ty + 8 * i) * DMODEL + n0 + tx];
    __syncthreads();
#pragma unroll
    for (int i = 0; i < 4; i++) {
        int n = n0 + ty + 8 * i, k = k0 + tx;
        float v = t[tx][ty + 8 * i];
        __nv_bfloat16 h = __float2bfloat16(v);
        __nv_bfloat16 l = __float2bfloat16(v - __bfloat162float(h));
        O[(size_t)n * KBIG + k]              = h;
        O[(size_t)n * KBIG + DMODEL + k]     = h;
        O[(size_t)n * KBIG + 2 * DMODEL + k] = l;
    }
}

// V fp32 [b*S+s][h*64+d] -> transposed bf16 hi/lo [bh][d][s]
__global__ __launch_bounds__(256) void cvt_vt(const float* __restrict__ V,
                                              __nv_bfloat16* __restrict__ Oh,
                                              __nv_bfloat16* __restrict__ Ol)
{
    __shared__ float t[64][65];
    const int tid = threadIdx.x;
    const int s0  = blockIdx.x * 64;
    const int bh  = blockIdx.y;
    const int b   = bh >> 4, h = bh & 15;
#pragma unroll
    for (int i = 0; i < 16; i++) {
        int u = tid + i * 256;
        int s = u >> 6, d = u & 63;
        t[s][d] = V[((size_t)(b * S_LEN) + s0 + s) * DMODEL + h * 64 + d];
    }
    __syncthreads();
    const int d  = tid >> 2;
    const int jg = tid & 3;
    __nv_bfloat16 hv[16], lv[16];
#pragma unroll
    for (int jj = 0; jj < 16; jj++) {
        float v = t[jg * 16 + jj][d];
        hv[jj] = __float2bfloat16(v);
        lv[jj] = __float2bfloat16(v - __bfloat162float(hv[jj]));
    }
    size_t dst = ((size_t)bh * HDIM + d) * S_LEN + s0 + jg * 16;
    ((uint4*)(Oh + dst))[0] = ((uint4*)hv)[0];
    ((uint4*)(Oh + dst))[1] = ((uint4*)hv)[1];
    ((uint4*)(Ol + dst))[0] = ((uint4*)lv)[0];
    ((uint4*)(Ol + dst))[1] = ((uint4*)lv)[1];
}

// ---------------- bf16 HMMA GEMM (R12 mainloop + staged fused epilogue) ------
// CTA 128x128, K chunk 64, 2-stage cp.async, 8 warps (64x32 warp tile).
// fuse_qk=1: z=0 -> (H0,L0), z=1 -> (H1,L1) head-split bf16 via smem staging;
//            z=2 -> Cf fp32.   fuse_qk=0: Cf fp32 (+bias).
__global__ __launch_bounds__(256) void gemm_mma(
    const __nv_bfloat16* __restrict__ A,
    const __nv_bfloat16* __restrict__ B0, const __nv_bfloat16* __restrict__ B1,
    const __nv_bfloat16* __restrict__ B2,
    float* Cf,
    __nv_bfloat16* H0, __nv_bfloat16* L0,
    __nv_bfloat16* H1, __nv_bfloat16* L1,
    const float* __restrict__ bias, int fuse_qk)
{
    extern __shared__ __align__(1024) unsigned char dsm[];

    const __nv_bfloat16* Bt = (blockIdx.z == 0) ? B0 : (blockIdx.z == 1) ? B1 : B2;

    const int tid  = threadIdx.x;
    const int wid  = tid >> 5;
    const int lane = tid & 31;
    const int bm   = blockIdx.y, bn = blockIdx.x;
    const int wm   = (wid & 1) * 64;
    const int wn   = (wid >> 1) * 32;

    const uint32_t s0 = smem_u32(dsm);
    const uint32_t sA = (s0 + 1023) & ~1023u;
    const uint32_t sB = sA + 32768;

    const int row0 = tid >> 3;
    const int seg  = tid & 7;
    const uint32_t swz = (uint32_t)((seg ^ (row0 & 7)) << 4);
    const __nv_bfloat16* aG = A  + (size_t)(bm * 128 + row0) * KBIG + seg * 8;
    const __nv_bfloat16* bG = Bt + (size_t)(bn * 128 + row0) * KBIG + seg * 8;
    const uint32_t stA = sA + row0 * 128 + swz;
    const uint32_t stB = sB + row0 * 128 + swz;

    uint32_t aBase[4], aMask[4];
#pragma unroll
    for (int mi = 0; mi < 4; mi++) {
        int r = wm + mi * 16 + (lane & 15);
        aBase[mi] = sA + r * 128;
        aMask[mi] = r & 7;
    }
    uint32_t bBase[2], bMask[2];
#pragma unroll
    for (int p = 0; p < 2; p++) {
        int r = wn + p * 16 + ((lane >> 4) << 3) + (lane & 7);
        bBase[p] = sB + r * 128;
        bMask[p] = r & 7;
    }
    const uint32_t kselA = (lane >> 4);
    const uint32_t kaddB = (lane >> 3) & 1;

    float acc[4][4][4];
#pragma unroll
    for (int mi = 0; mi < 4; mi++)
#pragma unroll
        for (int ni = 0; ni < 4; ni++)
#pragma unroll
            for (int r = 0; r < 4; r++) acc[mi][ni][r] = 0.0f;

    auto load_chunk = [&](int c, int buf) {
        const uint32_t bo = (uint32_t)buf * 16384;
        const __nv_bfloat16* ap = aG + c * 64;
        const __nv_bfloat16* bp = bG + c * 64;
#pragma unroll
        for (int i = 0; i < 4; i++) {
            cp_async16(stA + bo + i * 4096, ap + (size_t)i * 32 * KBIG);
            cp_async16(stB + bo + i * 4096, bp + (size_t)i * 32 * KBIG);
        }
        cp_commit();
    };

    load_chunk(0, 0);
    int buf = 0;
    for (int c = 0; c < KCH; c++) {
        cp_wait0();
        __syncthreads();
        if (c + 1 < KCH) load_chunk(c + 1, buf ^ 1);
        const uint32_t bo = (uint32_t)buf * 16384;
#pragma unroll
        for (int ks = 0; ks < 4; ks++) {
            uint32_t a[4][4], b[4][2];
#pragma unroll
            for (int mi = 0; mi < 4; mi++) {
                uint32_t u = (uint32_t)(ks * 2) + kselA;
                ldm_x4(a[mi][0], a[mi][1], a[mi][2], a[mi][3],
                       aBase[mi] + bo + ((u ^ aMask[mi]) << 4));
            }
#pragma unroll
            for (int p = 0; p < 2; p++) {
                uint32_t u = (uint32_t)(ks * 2) + kaddB;
                ldm_x4(b[2 * p][0], b[2 * p][1], b[2 * p + 1][0], b[2 * p + 1][1],
                       bBase[p] + bo + ((u ^ bMask[p]) << 4));
            }
#pragma unroll
            for (int mi = 0; mi < 4; mi++)
#pragma unroll
                for (int ni = 0; ni < 4; ni++)
                    mma_bf16(acc[mi][ni], a[mi], b[ni]);
        }
        buf ^= 1;
    }

    // ---- epilogue ----
    if (fuse_qk && blockIdx.z < 2) {
        // stage hi/lo bf16 in smem (row stride 272B -> bank-shift 4/row), then
        // write head layout [bh][s][64] with coalesced 16B stores.
        __nv_bfloat16* Oh = (blockIdx.z == 0) ? H0 : H1;
        __nv_bfloat16* Ol = (blockIdx.z == 0) ? L0 : L1;
        const uint32_t sHi = sA;              // 128 x 272B = 34816
        const uint32_t sLo = sA + 34816;
        __syncthreads();                      // all warps done reading sA/sB
#pragma unroll
        for (int mi = 0; mi < 4; mi++) {
#pragma unroll
            for (int ni = 0; ni < 4; ni++) {
#pragma unroll
                for (int half = 0; half < 2; half++) {
                    const int rowl = wm + mi * 16 + half * 8 + (lane >> 2);
                    const int coll = wn + ni * 8 + (lane & 3) * 2;
                    const float a0 = acc[mi][ni][half * 2 + 0];
                    const float a1 = acc[mi][ni][half * 2 + 1];
                    *(uint32_t*)(dsm + (sHi - s0) + rowl * 272 + coll * 2) =
                        packbf2(a0, a1);
                    *(uint32_t*)(dsm + (sLo - s0) + rowl * 272 + coll * 2) =
                        packbf2(a0 - bf16rt(a0), a1 - bf16rt(a1));
                }
            }
        }
        __syncthreads();
#pragma unroll
        for (int it = 0; it < 8; it++) {
            const int c     = tid + it * 256;          // 0..2047 (16B chunks)
            const int row   = c >> 4;                  // 0..127
            const int dch   = c & 15;                  // 16 chunks per 256B row
            const int hh    = dch >> 3;                // head within CTA (0/1)
            const int d8    = (dch & 7) * 8;           // col within head
            const int m     = bm * 128 + row;
            const int bb    = m >> 11, s = m & 2047;
            const int hg    = bn * 2 + hh;
            const size_t dst = ((size_t)(bb * NHEAD + hg) * S_LEN + s) * HDIM + d8;
            const uint32_t src = row * 272 + dch * 16;
            *(uint4*)(Oh + dst) = *(const uint4*)(dsm + (sHi - s0) + src);
            *(uint4*)(Ol + dst) = *(const uint4*)(dsm + (sLo - s0) + src);
        }
    } else {
        const int rbase = bm * 128 + wm + (lane >> 2);
        const int cbase = bn * 128 + wn + (lane & 3) * 2;
#pragma unroll
        for (int mi = 0; mi < 4; mi++) {
#pragma unroll
            for (int ni = 0; ni < 4; ni++) {
                const int col = cbase + ni * 8;
                float b0 = 0.0f, b1 = 0.0f;
                if (bias != nullptr) { b0 = bias[col]; b1 = bias[col + 1]; }
                float2 v01, v23;
                v01.x = acc[mi][ni][0] + b0; v01.y = acc[mi][ni][1] + b1;
                v23.x = acc[mi][ni][2] + b0; v23.y = acc[mi][ni][3] + b1;
                *(float2*)(Cf + (size_t)(rbase + mi * 16)     * DMODEL + col) = v01;
                *(float2*)(Cf + (size_t)(rbase + mi * 16 + 8) * DMODEL + col) = v23;
            }
        }
    }
}

// ---------------- HMMA flash attention (R12 mainloop + staged cbig epilogue) --
// grid (16, 32): CTA = 128 q-rows; 8 warps x 16 rows; k-tiles of 64; 96KB smem.
__global__ __launch_bounds__(256, 2) void flash_mma(
    const __nv_bfloat16* __restrict__ Qh, const __nv_bfloat16* __restrict__ Ql,
    const __nv_bfloat16* __restrict__ Kh, const __nv_bfloat16* __restrict__ Kl,
    const __nv_bfloat16* __restrict__ Vth, const __nv_bfloat16* __restrict__ Vtl,
    __nv_bfloat16* __restrict__ Cbig)
{
    extern __shared__ __align__(1024) unsigned char dsm[];
    const int tid  = threadIdx.x;
    const int wid  = tid >> 5;
    const int lane = tid & 31;
    const int qt   = (int)gridDim.x - 1 - (int)blockIdx.x;   // big tiles first
    const int bh   = blockIdx.y;
    const int b    = bh >> 4, h = bh & 15;

    const uint32_t s0   = smem_u32(dsm);
    const uint32_t sQh  = (s0 + 1023) & ~1023u;
    const uint32_t sQl  = sQh + 16384;
    const uint32_t sStg = sQh + 32768;          // 2 x 32768

    // ---- load Q tile (128 rows x 128B) hi+lo, swizzled ----
    {
        const __nv_bfloat16* qh = Qh + ((size_t)bh * S_LEN + qt * 128) * HDIM;
        const __nv_bfloat16* ql = Ql + ((size_t)bh * S_LEN + qt * 128) * HDIM;
#pragma unroll
        for (int i = 0; i < 4; i++) {
            int u   = tid + i * 256;
            int row = u >> 3, seg = u & 7;
            uint32_t off = row * 128 + (((uint32_t)(seg ^ (row & 7))) << 4);
            *(uint4*)(dsm + (sQh - s0) + off) = *(const uint4*)(qh + (size_t)row * HDIM + seg * 8);
            *(uint4*)(dsm + (sQl - s0) + off) = *(const uint4*)(ql + (size_t)row * HDIM + seg * 8);
        }
    }

    // ---- producer: K/V tile prefetch ----
    const int prow = tid >> 3;
    const int pseg = tid & 7;
    const uint32_t psw = ((uint32_t)(pseg ^ (prow & 7))) << 4;
    auto prefetch = [&](int kt, int bufi) {
        const uint32_t so = sStg + (uint32_t)bufi * 32768;
        const __nv_bfloat16* khG = Kh  + ((size_t)bh * S_LEN + kt * 64) * HDIM;
        const __nv_bfloat16* klG = Kl  + ((size_t)bh * S_LEN + kt * 64) * HDIM;
        const __nv_bfloat16* vhG = Vth + ((size_t)bh * HDIM) * S_LEN + kt * 64;
        const __nv_bfloat16* vlG = Vtl + ((size_t)bh * HDIM) * S_LEN + kt * 64;
#pragma unroll
        for (int i = 0; i < 2; i++) {
            int row = prow + i * 32;
            uint32_t off = row * 128 + psw;
            cp_async16(so +     0 + off, khG + (size_t)row * HDIM  + pseg * 8);
            cp_async16(so +  8192 + off, klG + (size_t)row * HDIM  + pseg * 8);
            cp_async16(so + 16384 + off, vhG + (size_t)row * S_LEN + pseg * 8);
            cp_async16(so + 24576 + off, vlG + (size_t)row * S_LEN + pseg * 8);
        }
        cp_commit();
    };

    // ---- consumer addressing ----
    const int qrow      = wid * 16 + (lane & 15);
    const uint32_t qOff = (uint32_t)qrow * 128;
    const uint32_t qMsk = qrow & 7;
    const uint32_t kselA = lane >> 4;
    uint32_t bOff[4], bMsk[4];
#pragma unroll
    for (int np = 0; np < 4; np++) {
        int r = np * 16 + ((lane >> 4) << 3) + (lane & 7);
        bOff[np] = (uint32_t)r * 128;
        bMsk[np] = r & 7;
    }
    const uint32_t kaddB = (lane >> 3) & 1;

    float o[8][4];
#pragma unroll
    for (int n = 0; n < 8; n++)
#pragma unroll
        for (int r = 0; r < 4; r++) o[n][r] = 0.0f;
    float m0 = -1.0e30f, m1 = -1.0e30f, l0 = 0.0f, l1 = 0.0f;

    const int ktn = 2 * qt + 2;
    prefetch(0, 0);
    int buf = 0;
    for (int kt = 0; kt < ktn; kt++) {
        cp_wait0();
        __syncthreads();
        if (kt + 1 < ktn) prefetch(kt + 1, buf ^ 1);
        const uint32_t so = sStg + (uint32_t)buf * 32768;
        buf ^= 1;

        if (kt * 64 > qt * 128 + wid * 16 + 15) continue;   // fully masked for warp

        // ---- S = Q K^T (3-pass hi/lo) ----
        float s[8][4];
#pragma unroll
        for (int n = 0; n < 8; n++)
#pragma unroll
            for (int r = 0; r < 4; r++) s[n][r] = 0.0f;
#pragma unroll
        for (int ks = 0; ks < 4; ks++) {
            uint32_t aH[4], aL[4];
            uint32_t ua = (uint32_t)(ks * 2) + kselA;
            ldm_x4(aH[0], aH[1], aH[2], aH[3], sQh + qOff + ((ua ^ qMsk) << 4));
            ldm_x4(aL[0], aL[1], aL[2], aL[3], sQl + qOff + ((ua ^ qMsk) << 4));
            uint32_t ub = (uint32_t)(ks * 2) + kaddB;
#pragma unroll
            for (int np = 0; np < 4; np++) {
                uint32_t bh2[2][2], bl2[2][2];
                uint32_t off = bOff[np] + ((ub ^ bMsk[np]) << 4);
                ldm_x4(bh2[0][0], bh2[0][1], bh2[1][0], bh2[1][1], so + 0    + off);
                ldm_x4(bl2[0][0], bl2[0][1], bl2[1][0], bl2[1][1], so + 8192 + off);
#pragma unroll
                for (int u = 0; u < 2; u++) {
                    mma_bf16(s[2 * np + u], aH, bh2[u]);
                    mma_bf16(s[2 * np + u], aL, bh2[u]);
                    mma_bf16(s[2 * np + u], aH, bl2[u]);
                }
            }
        }

        // ---- causal mask ----
        const int rg0 = qt * 128 + wid * 16 + (lane >> 2);
        if (kt * 64 + 63 > rg0) {
#pragma unroll
            for (int n = 0; n < 8; n++) {
                int cg = kt * 64 + n * 8 + (lane & 3) * 2;
                if (cg     > rg0)     s[n][0] = -1.0e30f;
                if (cg + 1 > rg0)     s[n][1] = -1.0e30f;
                if (cg     > rg0 + 8) s[n][2] = -1.0e30f;
                if (cg + 1 > rg0 + 8) s[n][3] = -1.0e30f;
            }
        }

        // ---- online softmax ----
        float mx0 = -1.0e30f, mx1 = -1.0e30f;
#pragma unroll
        for (int n = 0; n < 8; n++) {
            mx0 = fmaxf(mx0, fmaxf(s[n][0], s[n][1]));
            mx1 = fmaxf(mx1, fmaxf(s[n][2], s[n][3]));
        }
        mx0 = fmaxf(mx0, __shfl_xor_sync(0xffffffffu, mx0, 1));
        mx0 = fmaxf(mx0, __shfl_xor_sync(0xffffffffu, mx0, 2));
        mx1 = fmaxf(mx1, __shfl_xor_sync(0xffffffffu, mx1, 1));
        mx1 = fmaxf(mx1, __shfl_xor_sync(0xffffffffu, mx1, 2));
        const float mn0 = fmaxf(m0, mx0), mn1 = fmaxf(m1, mx1);
        const float sc0 = __expf(m0 - mn0), sc1 = __expf(m1 - mn1);
        float rs0 = 0.0f, rs1 = 0.0f;
#pragma unroll
        for (int n = 0; n < 8; n++) {
            s[n][0] = __expf(s[n][0] - mn0);
            s[n][1] = __expf(s[n][1] - mn0);
            s[n][2] = __expf(s[n][2] - mn1);
            s[n][3] = __expf(s[n][3] - mn1);
            rs0 += s[n][0] + s[n][1];
            rs1 += s[n][2] + s[n][3];
        }
        rs0 += __shfl_xor_sync(0xffffffffu, rs0, 1);
        rs0 += __shfl_xor_sync(0xffffffffu, rs0, 2);
        rs1 += __shfl_xor_sync(0xffffffffu, rs1, 1);
        rs1 += __shfl_xor_sync(0xffffffffu, rs1, 2);
        m0 = mn0; m1 = mn1;
        l0 = l0 * sc0 + rs0; l1 = l1 * sc1 + rs1;
#pragma unroll
        for (int n = 0; n < 8; n++) {
            o[n][0] *= sc0; o[n][1] *= sc0;
            o[n][2] *= sc1; o[n][3] *= sc1;
        }

        // ---- P fragments (hi + lo), FA2 accumulator->A mapping ----
        uint32_t pH[4][4], pL[4][4];
#pragma unroll
        for (int f = 0; f < 4; f++) {
            const int n0i = 2 * f, n1i = 2 * f + 1;
            pH[f][0] = packbf2(s[n0i][0], s[n0i][1]);
            pH[f][1] = packbf2(s[n0i][2], s[n0i][3]);
            pH[f][2] = packbf2(s[n1i][0], s[n1i][1]);
            pH[f][3] = packbf2(s[n1i][2], s[n1i][3]);
            pL[f][0] = packbf2(s[n0i][0] - bf16rt(s[n0i][0]), s[n0i][1] - bf16rt(s[n0i][1]));
            pL[f][1] = packbf2(s[n0i][2] - bf16rt(s[n0i][2]), s[n0i][3] - bf16rt(s[n0i][3]));
            pL[f][2] = packbf2(s[n1i][0] - bf16rt(s[n1i][0]), s[n1i][1] - bf16rt(s[n1i][1]));
            pL[f][3] = packbf2(s[n1i][2] - bf16rt(s[n1i][2]), s[n1i][3] - bf16rt(s[n1i][3]));
        }

        // ---- O += P V (3-pass) ----
#pragma unroll
        for (int f = 0; f < 4; f++) {
            uint32_t ub = (uint32_t)(f * 2) + kaddB;
#pragma unroll
            for (int np = 0; np < 4; np++) {
                uint32_t bvh[2][2], bvl[2][2];
                uint32_t off = bOff[np] + ((ub ^ bMsk[np]) << 4);
                ldm_x4(bvh[0][0], bvh[0][1], bvh[1][0], bvh[1][1], so + 16384 + off);
                ldm_x4(bvl[0][0], bvl[0][1], bvl[1][0], bvl[1][1], so + 24576 + off);
#pragma unroll
                for (int u = 0; u < 2; u++) {
                    mma_bf16(o[2 * np + u], pH[f], bvh[u]);
                    mma_bf16(o[2 * np + u], pL[f], bvh[u]);
                    mma_bf16(o[2 * np + u], pH[f], bvl[u]);
                }
            }
        }
    }

    // ---- staged epilogue: normalize, split hi/lo, write cbig [hi|lo|hi] ----
    __syncthreads();                      // all warps done with stage buffers
    const uint32_t sHi = sStg;            // 128 x 144B = 18432
    const uint32_t sLo = sStg + 18432;
    const float inv0 = 1.0f / l0, inv1 = 1.0f / l1;
#pragma unroll
    for (int n = 0; n < 8; n++) {
#pragma unroll
        for (int half = 0; half < 2; half++) {
            const int rowl = wid * 16 + half * 8 + (lane >> 2);
            const int coll = n * 8 + (lane & 3) * 2;
            const float inv = half ? inv1 : inv0;
            const float a0 = o[n][half * 2 + 0] * inv;
            const float a1 = o[n][half * 2 + 1] * inv;
            *(uint32_t*)(dsm + (sHi - s0) + rowl * 144 + coll * 2) = packbf2(a0, a1);
            *(uint32_t*)(dsm + (sLo - s0) + rowl * 144 + coll * 2) =
                packbf2(a0 - bf16rt(a0), a1 - bf16rt(a1));
        }
    }
    __syncthreads();
    const size_t mbase = (size_t)b * S_LEN + qt * 128;
#pragma unroll
    for (int it = 0; it < 4; it++) {
        const int c   = tid + it * 256;   // 0..1023 (16B chunks)
        const int row = c >> 3;           // 0..127
        const int ch  = c & 7;            // 8 chunks per 128B row
        const uint32_t src = row * 144 + ch * 16;
        uint4 hv = *(const uint4*)(dsm + (sHi - s0) + src);
        uint4 lv = *(const uint4*)(dsm + (sLo - s0) + src);
        __nv_bfloat16* baseP = Cbig + (mbase + row) * KBIG + h * 64 + ch * 8;
        *(uint4*)(baseP)              = hv;
        *(uint4*)(baseP + DMODEL)     = lv;
        *(uint4*)(baseP + 2 * DMODEL) = hv;
    }
}

// ---------------- launcher ----------------
extern "C" void kernel_launch(void* const* d_in, const int* in_sizes, int n_in,
                              void* d_out, int out_size)
{
    const float* X  = (const float*)d_in[0];
    const float* Wq = (const float*)d_in[1];
    const float* Wk = (const float*)d_in[2];
    const float* Wv = (const float*)d_in[3];
    const float* Wo = (const float*)d_in[4];
    const float* bo = (const float*)d_in[5];
    float* out = (float*)d_out;

    __nv_bfloat16 *xbig, *cbig, *wqb, *wkb, *wvb, *wob;
    __nv_bfloat16 *qh, *ql, *kh, *kl, *vth, *vtl;
    float *v;
    cudaGetSymbolAddress((void**)&xbig, g_xbig);
    cudaGetSymbolAddress((void**)&cbig, g_cbig);
    cudaGetSymbolAddress((void**)&wqb,  g_wqb);
    cudaGetSymbolAddress((void**)&wkb,  g_wkb);
    cudaGetSymbolAddress((void**)&wvb,  g_wvb);
    cudaGetSymbolAddress((void**)&wob,  g_wob);
    cudaGetSymbolAddress((void**)&v,    g_v);
    cudaGetSymbolAddress((void**)&qh,   g_qh);
    cudaGetSymbolAddress((void**)&ql,   g_ql);
    cudaGetSymbolAddress((void**)&kh,   g_kh);
    cudaGetSymbolAddress((void**)&kl,   g_kl);
    cudaGetSymbolAddress((void**)&vth,  g_vth);
    cudaGetSymbolAddress((void**)&vtl,  g_vtl);

    const int SMEM_GEMM = 69632 + 1024;   // mainloop 64KB; staging 2x34816
    const int SMEM_FA   = 98304 + 1024;
    cudaFuncSetAttribute(gemm_mma, cudaFuncAttributeMaxDynamicSharedMemorySize, SMEM_GEMM);
    cudaFuncSetAttribute(flash_mma, cudaFuncAttributeMaxDynamicSharedMemorySize, SMEM_FA);

    // conversions
    cvt_x<<<MROWS * DMODEL / (256 * 4), 256>>>(X, xbig);
    cvt_w4<<<dim3(DMODEL / 32, DMODEL / 32, 4), dim3(32, 8)>>>(
        Wq, Wk, Wv, Wo, wqb, wkb, wvb, wob);

    // QKV projection: Q,K -> bf16 head-split (staged epilogue); V -> fp32
    gemm_mma<<<dim3(DMODEL / 128, MROWS / 128, 3), 256, SMEM_GEMM>>>(
        xbig, wqb, wkb, wvb, v, qh, ql, kh, kl, nullptr, 1);

    // V transpose + hi/lo split
    cvt_vt<<<dim3(S_LEN / 64, NBH), 256>>>(v, vth, vtl);

    // flash attention (HMMA), writes cbig directly (staged epilogue)
    flash_mma<<<dim3(S_LEN / 128, NBH), 256, SMEM_FA>>>(qh, ql, kh, kl, vth, vtl, cbig);

    // output projection (fp32 out + bias)
    gemm_mma<<<dim3(DMODEL / 128, MROWS / 128, 1), 256, SMEM_GEMM>>>(
        cbig, wob, wob, wob, out, nullptr, nullptr, nullptr, nullptr, bo, 0);
}

// round 14
// speedup vs baseline: 1.1710x; 1.0043x over previous
#include <cuda_runtime.h>
#include <cuda_bf16.h>
#include <stdint.h>
#include <math.h>

#define BATCH   2
#define S_LEN   2048
#define DMODEL  1024
#define NHEAD   16
#define HDIM    64
#define MROWS   (BATCH * S_LEN)   // 4096
#define KBIG    (3 * DMODEL)      // 3072: B=[hi|hi|lo] (weights)
#define KA      (2 * DMODEL)      // 2048: A=[hi|lo], chunk c>=32 remaps to hi
#define KCH     (KBIG / 64)       // 48 chunks of K=64
#define NBH     (BATCH * NHEAD)   // 32

// ---------------- scratch (allocation-free device globals) ----------------
__device__ __align__(16) __nv_bfloat16 g_xbig[MROWS * KA];     // 16MB
__device__ __align__(16) __nv_bfloat16 g_cbig[MROWS * KA];     // 16MB
__device__ __align__(16) __nv_bfloat16 g_wqb[DMODEL * KBIG];
__device__ __align__(16) __nv_bfloat16 g_wkb[DMODEL * KBIG];
__device__ __align__(16) __nv_bfloat16 g_wvb[DMODEL * KBIG];
__device__ __align__(16) __nv_bfloat16 g_wob[DMODEL * KBIG];
// attention bf16 hi/lo operands
__device__ __align__(16) __nv_bfloat16 g_qh[NBH * S_LEN * HDIM];
__device__ __align__(16) __nv_bfloat16 g_ql[NBH * S_LEN * HDIM];
__device__ __align__(16) __nv_bfloat16 g_kh[NBH * S_LEN * HDIM];
__device__ __align__(16) __nv_bfloat16 g_kl[NBH * S_LEN * HDIM];
__device__ __align__(16) __nv_bfloat16 g_vth[NBH * HDIM * S_LEN];  // transposed
__device__ __align__(16) __nv_bfloat16 g_vtl[NBH * HDIM * S_LEN];

// ---------------- PTX helpers (all legal on plain sm_103) ----------------
__device__ __forceinline__ uint32_t smem_u32(const void* p) {
    uint32_t a;
    asm("{ .reg .u64 t; cvta.to.shared.u64 t, %1; cvt.u32.u64 %0, t; }" : "=r"(a) : "l"(p));
    return a;
}
__device__ __forceinline__ void cp_async16(uint32_t saddr, const void* gaddr) {
    asm volatile("cp.async.cg.shared.global [%0], [%1], 16;" :: "r"(saddr), "l"(gaddr));
}
__device__ __forceinline__ void cp_commit() {
    asm volatile("cp.async.commit_group;" ::: "memory");
}
__device__ __forceinline__ void cp_wait0() {
    asm volatile("cp.async.wait_group 0;" ::: "memory");
}
__device__ __forceinline__ void ldm_x4(uint32_t& r0, uint32_t& r1, uint32_t& r2, uint32_t& r3,
                                       uint32_t addr) {
    asm volatile("ldmatrix.sync.aligned.m8n8.x4.shared.b16 {%0,%1,%2,%3}, [%4];"
                 : "=r"(r0), "=r"(r1), "=r"(r2), "=r"(r3) : "r"(addr));
}
__device__ __forceinline__ void mma_bf16(float* d, const uint32_t* a, const uint32_t* b) {
    asm volatile(
        "mma.sync.aligned.m16n8k16.row.col.f32.bf16.bf16.f32 "
        "{%0,%1,%2,%3}, {%4,%5,%6,%7}, {%8,%9}, {%0,%1,%2,%3};"
        : "+f"(d[0]), "+f"(d[1]), "+f"(d[2]), "+f"(d[3])
        : "r"(a[0]), "r"(a[1]), "r"(a[2]), "r"(a[3]), "r"(b[0]), "r"(b[1]));
}
__device__ __forceinline__ uint32_t packbf2(float a, float b) {
    __nv_bfloat162 t = __floats2bfloat162_rn(a, b);
    return *reinterpret_cast<uint32_t*>(&t);
}
__device__ __forceinline__ float bf16rt(float v) {
    return __bfloat162float(__float2bfloat16(v));
}

// ---------------- conversion: fp32 -> bf16 [hi | lo], K'=2048 ----------------
__global__ __launch_bounds__(256) void cvt_x(const float* __restrict__ X,
                                             __nv_bfloat16* __restrict__ O)
{
    int idx = blockIdx.x * 256 + threadIdx.x;
    int m   = idx >> 8;
    int k4  = (idx & 255) << 2;
    float4 v = *(const float4*)(X + (size_t)m * DMODEL + k4);
    float f[4] = {v.x, v.y, v.z, v.w};
    __nv_bfloat16 h[4], l[4];
#pragma unroll
    for (int i = 0; i < 4; i++) {
        h[i] = __float2bfloat16(f[i]);
        l[i] = __float2bfloat16(f[i] - __bfloat162float(h[i]));
    }
    __nv_bfloat162 h01, h23, l01, l23;
    h01.x = h[0]; h01.y = h[1]; h23.x = h[2]; h23.y = h[3];
    l01.x = l[0]; l01.y = l[1]; l23.x = l[2]; l23.y = l[3];
    __nv_bfloat162* p0 = (__nv_bfloat162*)(O + (size_t)m * KA + k4);
    __nv_bfloat162* p1 = (__nv_bfloat162*)(O + (size_t)m * KA + DMODEL + k4);
    p0[0] = h01; p0[1] = h23;      // hi
    p1[0] = l01; p1[1] = l23;      // lo
}

// all four weight conversions in one launch: z selects (W, O); [hi|hi|lo], K'=3072
__global__ __launch_bounds__(256) void cvt_w4(
    const float* __restrict__ W0, const float* __restrict__ W1,
    const float* __restrict__ W2, const float* __restrict__ W3,
    __nv_bfloat16* O0, __nv_bfloat16* O1, __nv_bfloat16* O2, __nv_bfloat16* O3)
{
    const float* W = (blockIdx.z == 0) ? W0 : (blockIdx.z == 1) ? W1
                   : (blockIdx.z == 2) ? W2 : W3;
    __nv_bfloat16* O = (blockIdx.z == 0) ? O0 : (blockIdx.z == 1) ? O1
                     : (blockIdx.z == 2) ? O2 : O3;
    __shared__ float t[32][33];
    int n0 = blockIdx.x * 32, k0 = blockIdx.y * 32;
    int tx = threadIdx.x, ty = threadIdx.y;
#pragma unroll
    for (int i = 0; i < 4; i++)
        t[ty + 8 * i][tx] = W[(size_t)(k0 + ty + 8 * i) * DMODEL + n0 + tx];
    __syncthreads();
#pragma unroll
    for (int i = 0; i < 4; i++) {
        int n = n0 + ty + 8 * i, k = k0 + tx;
        float v = t[tx][ty + 8 * i];
        __nv_bfloat16 h = __float2bfloat16(v);
        __nv_bfloat16 l = __float2bfloat16(v - __bfloat162float(h));
        O[(size_t)n * KBIG + k]              = h;
        O[(size_t)n * KBIG + DMODEL + k]     = h;
        O[(size_t)n * KBIG + 2 * DMODEL + k] = l;
    }
}

// ---------------- bf16 HMMA GEMM (R13 mainloop + fused epilogues) ------------
// CTA 128x128, K chunk 64 (48 chunks; A chunk c>=32 remaps to c-32), 8 warps.
// fuse_qk=1: z=0 -> (H0,L0) head-split; z=1 -> (H1,L1); z=2 -> (Vh,Vl) TRANSPOSED.
// fuse_qk=0: Cf fp32 (+bias).
__global__ __launch_bounds__(256) void gemm_mma(
    const __nv_bfloat16* __restrict__ A,
    const __nv_bfloat16* __restrict__ B0, const __nv_bfloat16* __restrict__ B1,
    const __nv_bfloat16* __restrict__ B2,
    float* Cf,
    __nv_bfloat16* H0, __nv_bfloat16* L0,
    __nv_bfloat16* H1, __nv_bfloat16* L1,
    __nv_bfloat16* Vh, __nv_bfloat16* Vl,
    const float* __restrict__ bias, int fuse_qk)
{
    extern __shared__ __align__(1024) unsigned char dsm[];

    const __nv_bfloat16* Bt = (blockIdx.z == 0) ? B0 : (blockIdx.z == 1) ? B1 : B2;

    const int tid  = threadIdx.x;
    const int wid  = tid >> 5;
    const int lane = tid & 31;
    const int bm   = blockIdx.y, bn = blockIdx.x;
    const int wm   = (wid & 1) * 64;
    const int wn   = (wid >> 1) * 32;

    const uint32_t s0 = smem_u32(dsm);
    const uint32_t sA = (s0 + 1023) & ~1023u;
    const uint32_t sB = sA + 32768;

    const int row0 = tid >> 3;
    const int seg  = tid & 7;
    const uint32_t swz = (uint32_t)((seg ^ (row0 & 7)) << 4);
    const __nv_bfloat16* aG = A  + (size_t)(bm * 128 + row0) * KA + seg * 8;
    const __nv_bfloat16* bG = Bt + (size_t)(bn * 128 + row0) * KBIG + seg * 8;
    const uint32_t stA = sA + row0 * 128 + swz;
    const uint32_t stB = sB + row0 * 128 + swz;

    uint32_t aBase[4], aMask[4];
#pragma unroll
    for (int mi = 0; mi < 4; mi++) {
        int r = wm + mi * 16 + (lane & 15);
        aBase[mi] = sA + r * 128;
        aMask[mi] = r & 7;
    }
    uint32_t bBase[2], bMask[2];
#pragma unroll
    for (int p = 0; p < 2; p++) {
        int r = wn + p * 16 + ((lane >> 4) << 3) + (lane & 7);
        bBase[p] = sB + r * 128;
        bMask[p] = r & 7;
    }
    const uint32_t kselA = (lane >> 4);
    const uint32_t kaddB = (lane >> 3) & 1;

    float acc[4][4][4];
#pragma unroll
    for (int mi = 0; mi < 4; mi++)
#pragma unroll
        for (int ni = 0; ni < 4; ni++)
#pragma unroll
            for (int r = 0; r < 4; r++) acc[mi][ni][r] = 0.0f;

    auto load_chunk = [&](int c, int buf) {
        const uint32_t bo = (uint32_t)buf * 16384;
        const int ca = (c < 32) ? c : (c - 32);          // A: [hi|lo], seg2 -> hi
        const __nv_bfloat16* ap = aG + ca * 64;
        const __nv_bfloat16* bp = bG + c * 64;
#pragma unroll
        for (int i = 0; i < 4; i++) {
            cp_async16(stA + bo + i * 4096, ap + (size_t)i * 32 * KA);
            cp_async16(stB + bo + i * 4096, bp + (size_t)i * 32 * KBIG);
        }
        cp_commit();
    };

    load_chunk(0, 0);
    int buf = 0;
    for (int c = 0; c < KCH; c++) {
        cp_wait0();
        __syncthreads();
        if (c + 1 < KCH) load_chunk(c + 1, buf ^ 1);
        const uint32_t bo = (uint32_t)buf * 16384;
#pragma unroll
        for (int ks = 0; ks < 4; ks++) {
            uint32_t a[4][4], b[4][2];
#pragma unroll
            for (int mi = 0; mi < 4; mi++) {
                uint32_t u = (uint32_t)(ks * 2) + kselA;
                ldm_x4(a[mi][0], a[mi][1], a[mi][2], a[mi][3],
                       aBase[mi] + bo + ((u ^ aMask[mi]) << 4));
            }
#pragma unroll
            for (int p = 0; p < 2; p++) {
                uint32_t u = (uint32_t)(ks * 2) + kaddB;
                ldm_x4(b[2 * p][0], b[2 * p][1], b[2 * p + 1][0], b[2 * p + 1][1],
                       bBase[p] + bo + ((u ^ bMask[p]) << 4));
            }
#pragma unroll
            for (int mi = 0; mi < 4; mi++)
#pragma unroll
                for (int ni = 0; ni < 4; ni++)
                    mma_bf16(acc[mi][ni], a[mi], b[ni]);
        }
        buf ^= 1;
    }

    // ---- epilogue ----
    if (fuse_qk && blockIdx.z < 2) {
        // Q/K: stage hi/lo bf16 (row stride 272B), coalesced head-layout stores.
        __nv_bfloat16* Oh = (blockIdx.z == 0) ? H0 : H1;
        __nv_bfloat16* Ol = (blockIdx.z == 0) ? L0 : L1;
        const uint32_t sHi = sA;              // 128 x 272B = 34816
        const uint32_t sLo = sA + 34816;
        __syncthreads();
#pragma unroll
        for (int mi = 0; mi < 4; mi++) {
#pragma unroll
            for (int ni = 0; ni < 4; ni++) {
#pragma unroll
                for (int half = 0; half < 2; half++) {
                    const int rowl = wm + mi * 16 + half * 8 + (lane >> 2);
                    const int coll = wn + ni * 8 + (lane & 3) * 2;
                    const float a0 = acc[mi][ni][half * 2 + 0];
                    const float a1 = acc[mi][ni][half * 2 + 1];
                    *(uint32_t*)(dsm + (sHi - s0) + rowl * 272 + coll * 2) =
                        packbf2(a0, a1);
                    *(uint32_t*)(dsm + (sLo - s0) + rowl * 272 + coll * 2) =
                        packbf2(a0 - bf16rt(a0), a1 - bf16rt(a1));
                }
            }
        }
        __syncthreads();
#pragma unroll
        for (int it = 0; it < 8; it++) {
            const int c     = tid + it * 256;          // 0..2047 (16B chunks)
            const int row   = c >> 4;
            const int dch   = c & 15;
            const int hh    = dch >> 3;
            const int d8    = (dch & 7) * 8;
            const int m     = bm * 128 + row;
            const int bb    = m >> 11, s = m & 2047;
            const int hg    = bn * 2 + hh;
            const size_t dst = ((size_t)(bb * NHEAD + hg) * S_LEN + s) * HDIM + d8;
            const uint32_t src = row * 272 + dch * 16;
            *(uint4*)(Oh + dst) = *(const uint4*)(dsm + (sHi - s0) + src);
            *(uint4*)(Ol + dst) = *(const uint4*)(dsm + (sLo - s0) + src);
        }
    } else if (fuse_qk) {
        // V: stage hi/lo (row stride 260B), then TRANSPOSED coalesced stores
        // into [bh][d][s] layout (warp covers 256B contiguous in s).
        const uint32_t sHi = sA;              // 128 x 260B = 33280
        const uint32_t sLo = sA + 33280;      // total 66560 < 69632
        __syncthreads();
#pragma unroll
        for (int mi = 0; mi < 4; mi++) {
#pragma unroll
            for (int ni = 0; ni < 4; ni++) {
#pragma unroll
                for (int half = 0; half < 2; half++) {
                    const int rowl = wm + mi * 16 + half * 8 + (lane >> 2);
                    const int coll = wn + ni * 8 + (lane & 3) * 2;
                    const float a0 = acc[mi][ni][half * 2 + 0];
                    const float a1 = acc[mi][ni][half * 2 + 1];
                    *(uint32_t*)(dsm + (sHi - s0) + rowl * 260 + coll * 2) =
                        packbf2(a0, a1);
                    *(uint32_t*)(dsm + (sLo - s0) + rowl * 260 + coll * 2) =
                        packbf2(a0 - bf16rt(a0), a1 - bf16rt(a1));
                }
            }
        }
        __syncthreads();
        const int mg = bm * 128;
        const int bb = mg >> 11;
        const int sbase = mg & 2047;
#pragma unroll
        for (int it = 0; it < 8; it++) {
            const int c2   = tid + it * 256;           // 0..2047
            const int d128 = c2 >> 4;                  // 0..127 (2 heads x 64)
            const int sc   = c2 & 15;                  // 16B chunk along s
            unsigned short hv[8], lv[8];
#pragma unroll
            for (int j = 0; j < 8; j++) {
                const uint32_t src = (uint32_t)(sc * 8 + j) * 260 + d128 * 2;
                hv[j] = *(const unsigned short*)(dsm + (sHi - s0) + src);
                lv[j] = *(const unsigned short*)(dsm + (sLo - s0) + src);
            }
            const int d  = d128 & 63;
            const int hh = d128 >> 6;
            const int hg = bn * 2 + hh;
            const size_t dst = ((size_t)(bb * NHEAD + hg) * HDIM + d) * S_LEN
                             + sbase + sc * 8;
            *(uint4*)(Vh + dst) = *(const uint4*)hv;
            *(uint4*)(Vl + dst) = *(const uint4*)lv;
        }
    } else {
        const int rbase = bm * 128 + wm + (lane >> 2);
        const int cbase = bn * 128 + wn + (lane & 3) * 2;
#pragma unroll
        for (int mi = 0; mi < 4; mi++) {
#pragma unroll
            for (int ni = 0; ni < 4; ni++) {
                const int col = cbase + ni * 8;
                float b0 = 0.0f, b1 = 0.0f;
                if (bias != nullptr) { b0 = bias[col]; b1 = bias[col + 1]; }
                float2 v01, v23;
                v01.x = acc[mi][ni][0] + b0; v01.y = acc[mi][ni][1] + b1;
                v23.x = acc[mi][ni][2] + b0; v23.y = acc[mi][ni][3] + b1;
                *(float2*)(Cf + (size_t)(rbase + mi * 16)     * DMODEL + col) = v01;
                *(float2*)(Cf + (size_t)(rbase + mi * 16 + 8) * DMODEL + col) = v23;
            }
        }
    }
}

// ---------------- HMMA flash attention (R13, cbig now 2-segment) -------------
// grid (16, 32): CTA = 128 q-rows; 8 warps x 16 rows; k-tiles of 64; 96KB smem.
__global__ __launch_bounds__(256, 2) void flash_mma(
    const __nv_bfloat16* __restrict__ Qh, const __nv_bfloat16* __restrict__ Ql,
    const __nv_bfloat16* __restrict__ Kh, const __nv_bfloat16* __restrict__ Kl,
    const __nv_bfloat16* __restrict__ Vth, const __nv_bfloat16* __restrict__ Vtl,
    __nv_bfloat16* __restrict__ Cbig)
{
    extern __shared__ __align__(1024) unsigned char dsm[];
    const int tid  = threadIdx.x;
    const int wid  = tid >> 5;
    const int lane = tid & 31;
    const int qt   = (int)gridDim.x - 1 - (int)blockIdx.x;   // big tiles first
    const int bh   = blockIdx.y;
    const int b    = bh >> 4, h = bh & 15;

    const uint32_t s0   = smem_u32(dsm);
    const uint32_t sQh  = (s0 + 1023) & ~1023u;
    const uint32_t sQl  = sQh + 16384;
    const uint32_t sStg = sQh + 32768;          // 2 x 32768

    // ---- load Q tile (128 rows x 128B) hi+lo, swizzled ----
    {
        const __nv_bfloat16* qh = Qh + ((size_t)bh * S_LEN + qt * 128) * HDIM;
        const __nv_bfloat16* ql = Ql + ((size_t)bh * S_LEN + qt * 128) * HDIM;
#pragma unroll
        for (int i = 0; i < 4; i++) {
            int u   = tid + i * 256;
            int row = u >> 3, seg = u & 7;
            uint32_t off = row * 128 + (((uint32_t)(seg ^ (row & 7))) << 4);
            *(uint4*)(dsm + (sQh - s0) + off) = *(const uint4*)(qh + (size_t)row * HDIM + seg * 8);
            *(uint4*)(dsm + (sQl - s0) + off) = *(const uint4*)(ql + (size_t)row * HDIM + seg * 8);
        }
    }

    // ---- producer: K/V tile prefetch ----
    const int prow = tid >> 3;
    const int pseg = tid & 7;
    const uint32_t psw = ((uint32_t)(pseg ^ (prow & 7))) << 4;
    auto prefetch = [&](int kt, int bufi) {
        const uint32_t so = sStg + (uint32_t)bufi * 32768;
        const __nv_bfloat16* khG = Kh  + ((size_t)bh * S_LEN + kt * 64) * HDIM;
        const __nv_bfloat16* klG = Kl  + ((size_t)bh * S_LEN + kt * 64) * HDIM;
        const __nv_bfloat16* vhG = Vth + ((size_t)bh * HDIM) * S_LEN + kt * 64;
        const __nv_bfloat16* vlG = Vtl + ((size_t)bh * HDIM) * S_LEN + kt * 64;
#pragma unroll
        for (int i = 0; i < 2; i++) {
            int row = prow + i * 32;
            uint32_t off = row * 128 + psw;
            cp_async16(so +     0 + off, khG + (size_t)row * HDIM  + pseg * 8);
            cp_async16(so +  8192 + off, klG + (size_t)row * HDIM  + pseg * 8);
            cp_async16(so + 16384 + off, vhG + (size_t)row * S_LEN + pseg * 8);
            cp_async16(so + 24576 + off, vlG + (size_t)row * S_LEN + pseg * 8);
        }
        cp_commit();
    };

    // ---- consumer addressing ----
    const int qrow      = wid * 16 + (lane & 15);
    const uint32_t qOff = (uint32_t)qrow * 128;
    const uint32_t qMsk = qrow & 7;
    const uint32_t kselA = lane >> 4;
    uint32_t bOff[4], bMsk[4];
#pragma unroll
    for (int np = 0; np < 4; np++) {
        int r = np * 16 + ((lane >> 4) << 3) + (lane & 7);
        bOff[np] = (uint32_t)r * 128;
        bMsk[np] = r & 7;
    }
    const uint32_t kaddB = (lane >> 3) & 1;

    float o[8][4];
#pragma unroll
    for (int n = 0; n < 8; n++)
#pragma unroll
        for (int r = 0; r < 4; r++) o[n][r] = 0.0f;
    float m0 = -1.0e30f, m1 = -1.0e30f, l0 = 0.0f, l1 = 0.0f;

    const int ktn = 2 * qt + 2;
    prefetch(0, 0);
    int buf = 0;
    for (int kt = 0; kt < ktn; kt++) {
        cp_wait0();
        __syncthreads();
        if (kt + 1 < ktn) prefetch(kt + 1, buf ^ 1);
        const uint32_t so = sStg + (uint32_t)buf * 32768;
        buf ^= 1;

        if (kt * 64 > qt * 128 + wid * 16 + 15) continue;   // fully masked for warp

        // ---- S = Q K^T (3-pass hi/lo) ----
        float s[8][4];
#pragma unroll
        for (int n = 0; n < 8; n++)
#pragma unroll
            for (int r = 0; r < 4; r++) s[n][r] = 0.0f;
#pragma unroll
        for (int ks = 0; ks < 4; ks++) {
            uint32_t aH[4], aL[4];
            uint32_t ua = (uint32_t)(ks * 2) + kselA;
            ldm_x4(aH[0], aH[1], aH[2], aH[3], sQh + qOff + ((ua ^ qMsk) << 4));
            ldm_x4(aL[0], aL[1], aL[2], aL[3], sQl + qOff + ((ua ^ qMsk) << 4));
            uint32_t ub = (uint32_t)(ks * 2) + kaddB;
#pragma unroll
            for (int np = 0; np < 4; np++) {
                uint32_t bh2[2][2], bl2[2][2];
                uint32_t off = bOff[np] + ((ub ^ bMsk[np]) << 4);
                ldm_x4(bh2[0][0], bh2[0][1], bh2[1][0], bh2[1][1], so + 0    + off);
                ldm_x4(bl2[0][0], bl2[0][1], bl2[1][0], bl2[1][1], so + 8192 + off);
#pragma unroll
                for (int u = 0; u < 2; u++) {
                    mma_bf16(s[2 * np + u], aH, bh2[u]);
                    mma_bf16(s[2 * np + u], aL, bh2[u]);
                    mma_bf16(s[2 * np + u], aH, bl2[u]);
                }
            }
        }

        // ---- causal mask ----
        const int rg0 = qt * 128 + wid * 16 + (lane >> 2);
        if (kt * 64 + 63 > rg0) {
#pragma unroll
            for (int n = 0; n < 8; n++) {
                int cg = kt * 64 + n * 8 + (lane & 3) * 2;
                if (cg     > rg0)     s[n][0] = -1.0e30f;
                if (cg + 1 > rg0)     s[n][1] = -1.0e30f;
                if (cg     > rg0 + 8) s[n][2] = -1.0e30f;
                if (cg + 1 > rg0 + 8) s[n][3] = -1.0e30f;
            }
        }

        // ---- online softmax ----
        float mx0 = -1.0e30f, mx1 = -1.0e30f;
#pragma unroll
        for (int n = 0; n < 8; n++) {
            mx0 = fmaxf(mx0, fmaxf(s[n][0], s[n][1]));
            mx1 = fmaxf(mx1, fmaxf(s[n][2], s[n][3]));
        }
        mx0 = fmaxf(mx0, __shfl_xor_sync(0xffffffffu, mx0, 1));
        mx0 = fmaxf(mx0, __shfl_xor_sync(0xffffffffu, mx0, 2));
        mx1 = fmaxf(mx1, __shfl_xor_sync(0xffffffffu, mx1, 1));
        mx1 = fmaxf(mx1, __shfl_xor_sync(0xffffffffu, mx1, 2));
        const float mn0 = fmaxf(m0, mx0), mn1 = fmaxf(m1, mx1);
        const float sc0 = __expf(m0 - mn0), sc1 = __expf(m1 - mn1);
        float rs0 = 0.0f, rs1 = 0.0f;
#pragma unroll
        for (int n = 0; n < 8; n++) {
            s[n][0] = __expf(s[n][0] - mn0);
            s[n][1] = __expf(s[n][1] - mn0);
            s[n][2] = __expf(s[n][2] - mn1);
            s[n][3] = __expf(s[n][3] - mn1);
            rs0 += s[n][0] + s[n][1];
            rs1 += s[n][2] + s[n][3];
        }
        rs0 += __shfl_xor_sync(0xffffffffu, rs0, 1);
        rs0 += __shfl_xor_sync(0xffffffffu, rs0, 2);
        rs1 += __shfl_xor_sync(0xffffffffu, rs1, 1);
        rs1 += __shfl_xor_sync(0xffffffffu, rs1, 2);
        m0 = mn0; m1 = mn1;
        l0 = l0 * sc0 + rs0; l1 = l1 * sc1 + rs1;
#pragma unroll
        for (int n = 0; n < 8; n++) {
            o[n][0] *= sc0; o[n][1] *= sc0;
            o[n][2] *= sc1; o[n][3] *= sc1;
        }

        // ---- P fragments (hi + lo), FA2 accumulator->A mapping ----
        uint32_t pH[4][4], pL[4][4];
#pragma unroll
        for (int f = 0; f < 4; f++) {
            const int n0i = 2 * f, n1i = 2 * f + 1;
            pH[f][0] = packbf2(s[n0i][0], s[n0i][1]);
            pH[f][1] = packbf2(s[n0i][2], s[n0i][3]);
            pH[f][2] = packbf2(s[n1i][0], s[n1i][1]);
            pH[f][3] = packbf2(s[n1i][2], s[n1i][3]);
            pL[f][0] = packbf2(s[n0i][0] - bf16rt(s[n0i][0]), s[n0i][1] - bf16rt(s[n0i][1]));
            pL[f][1] = packbf2(s[n0i][2] - bf16rt(s[n0i][2]), s[n0i][3] - bf16rt(s[n0i][3]));
            pL[f][2] = packbf2(s[n1i][0] - bf16rt(s[n1i][0]), s[n1i][1] - bf16rt(s[n1i][1]));
            pL[f][3] = packbf2(s[n1i][2] - bf16rt(s[n1i][2]), s[n1i][3] - bf16rt(s[n1i][3]));
        }

        // ---- O += P V (3-pass) ----
#pragma unroll
        for (int f = 0; f < 4; f++) {
            uint32_t ub = (uint32_t)(f * 2) + kaddB;
#pragma unroll
            for (int np = 0; np < 4; np++) {
                uint32_t bvh[2][2], bvl[2][2];
                uint32_t off = bOff[np] + ((ub ^ bMsk[np]) << 4);
                ldm_x4(bvh[0][0], bvh[0][1], bvh[1][0], bvh[1][1], so + 16384 + off);
                ldm_x4(bvl[0][0], bvl[0][1], bvl[1][0], bvl[1][1], so + 24576 + off);
#pragma unroll
                for (int u = 0; u < 2; u++) {
                    mma_bf16(o[2 * np + u], pH[f], bvh[u]);
                    mma_bf16(o[2 * np + u], pL[f], bvh[u]);
                    mma_bf16(o[2 * np + u], pH[f], bvl[u]);
                }
            }
        }
    }

    // ---- staged epilogue: normalize, split hi/lo, write cbig [hi|lo] ----
    __syncthreads();                      // all warps done with stage buffers
    const uint32_t sHi = sStg;            // 128 x 144B = 18432
    const uint32_t sLo = sStg + 18432;
    const float inv0 = 1.0f / l0, inv1 = 1.0f / l1;
#pragma unroll
    for (int n = 0; n < 8; n++) {
#pragma unroll
        for (int half = 0; half < 2; half++) {
            const int rowl = wid * 16 + half * 8 + (lane >> 2);
            const int coll = n * 8 + (lane & 3) * 2;
            const float inv = half ? inv1 : inv0;
            const float a0 = o[n][half * 2 + 0] * inv;
            const float a1 = o[n][half * 2 + 1] * inv;
            *(uint32_t*)(dsm + (sHi - s0) + rowl * 144 + coll * 2) = packbf2(a0, a1);
            *(uint32_t*)(dsm + (sLo - s0) + rowl * 144 + coll * 2) =
                packbf2(a0 - bf16rt(a0), a1 - bf16rt(a1));
        }
    }
    __syncthreads();
    const size_t mbase = (size_t)b * S_LEN + qt * 128;
#pragma unroll
    for (int it = 0; it < 4; it++) {
        const int c   = tid + it * 256;   // 0..1023 (16B chunks)
        const int row = c >> 3;           // 0..127
        const int ch  = c & 7;            // 8 chunks per 128B row
        const uint32_t src = row * 144 + ch * 16;
        uint4 hv = *(const uint4*)(dsm + (sHi - s0) + src);
        uint4 lv = *(const uint4*)(dsm + (sLo - s0) + src);
        __nv_bfloat16* baseP = Cbig + (mbase + row) * KA + h * 64 + ch * 8;
        *(uint4*)(baseP)          = hv;
        *(uint4*)(baseP + DMODEL) = lv;
    }
}

// ---------------- launcher ----------------
extern "C" void kernel_launch(void* const* d_in, const int* in_sizes, int n_in,
                              void* d_out, int out_size)
{
    const float* X  = (const float*)d_in[0];
    const float* Wq = (const float*)d_in[1];
    const float* Wk = (const float*)d_in[2];
    const float* Wv = (const float*)d_in[3];
    const float* Wo = (const float*)d_in[4];
    const float* bo = (const float*)d_in[5];
    float* out = (float*)d_out;

    __nv_bfloat16 *xbig, *cbig, *wqb, *wkb, *wvb, *wob;
    __nv_bfloat16 *qh, *ql, *kh, *kl, *vth, *vtl;
    cudaGetSymbolAddress((void**)&xbig, g_xbig);
    cudaGetSymbolAddress((void**)&cbig, g_cbig);
    cudaGetSymbolAddress((void**)&wqb,  g_wqb);
    cudaGetSymbolAddress((void**)&wkb,  g_wkb);
    cudaGetSymbolAddress((void**)&wvb,  g_wvb);
    cudaGetSymbolAddress((void**)&wob,  g_wob);
    cudaGetSymbolAddress((void**)&qh,   g_qh);
    cudaGetSymbolAddress((void**)&ql,   g_ql);
    cudaGetSymbolAddress((void**)&kh,   g_kh);
    cudaGetSymbolAddress((void**)&kl,   g_kl);
    cudaGetSymbolAddress((void**)&vth,  g_vth);
    cudaGetSymbolAddress((void**)&vtl,  g_vtl);

    const int SMEM_GEMM = 69632 + 1024;   // mainloop 64KB; staging <= 2x34816
    const int SMEM_FA   = 98304 + 1024;
    cudaFuncSetAttribute(gemm_mma, cudaFuncAttributeMaxDynamicSharedMemorySize, SMEM_GEMM);
    cudaFuncSetAttribute(flash_mma, cudaFuncAttributeMaxDynamicSharedMemorySize, SMEM_FA);

    // conversions
    cvt_x<<<MROWS * DMODEL / (256 * 4), 256>>>(X, xbig);
    cvt_w4<<<dim3(DMODEL / 32, DMODEL / 32, 4), dim3(32, 8)>>>(
        Wq, Wk, Wv, Wo, wqb, wkb, wvb, wob);

    // QKV projection: Q,K -> head-split bf16; V -> transposed bf16 (all fused)
    gemm_mma<<<dim3(DMODEL / 128, MROWS / 128, 3), 256, SMEM_GEMM>>>(
        xbig, wqb, wkb, wvb, nullptr, qh, ql, kh, kl, vth, vtl, nullptr, 1);

    // flash attention (HMMA), writes cbig [hi|lo] directly
    flash_mma<<<dim3(S_LEN / 128, NBH), 256, SMEM_FA>>>(qh, ql, kh, kl, vth, vtl, cbig);

    // output projection (fp32 out + bias)
    gemm_mma<<<dim3(DMODEL / 128, MROWS / 128, 1), 256, SMEM_GEMM>>>(
        cbig, wob, wob, wob, out, nullptr, nullptr, nullptr, nullptr,
        nullptr, nullptr, bo, 0);
}